// round 2
// baseline (speedup 1.0000x reference)
#include <cuda_runtime.h>
#include <mma.h>
using namespace nvcuda;

#define BDIM   8192
#define KDIM   2336
#define NDIM   20000
#define NPAD   20032
#define ZW     2304   // width of z (NP+NA)
#define NPROW  2048
#define NAROW  256
#define NCROW  32

#define BM 128
#define BN 64
#define BK 32
#define NKT (KDIM / BK)   // 73
#define GM (BDIM / BM)    // 64
#define GN (NPAD / BN)    // 313

// Device scratch (allocation-free rule: __device__ globals)
__device__ float g_A[(size_t)BDIM * KDIM];      // packed A  [8192][2336]
__device__ float g_W[(size_t)KDIM * NPAD];      // packed B  [2336][20032], mask fused, zero pad
__device__ float g_scale[BDIM];                 // exp(log_lib)/rowsum

// ---------------------------------------------------------------------------
// Pack A = [z | cov] row-major, K contiguous
__global__ void build_A_kernel(const float* __restrict__ z,
                               const float* __restrict__ cov) {
    const int F4 = KDIM / 4;                    // 584
    int idx = blockIdx.x * blockDim.x + threadIdx.x;
    int total = BDIM * F4;
    if (idx >= total) return;
    int r  = idx / F4;
    int c4 = idx - r * F4;
    int c  = c4 * 4;
    float4 v;
    if (c < ZW) v = *reinterpret_cast<const float4*>(z + r * ZW + c);
    else        v = *reinterpret_cast<const float4*>(cov + r * NCROW + (c - ZW));
    reinterpret_cast<float4*>(g_A)[idx] = v;
}

// Pack B = [W_mask*mask ; W_addon*addon_mask ; W_cov], zero-padded to NPAD cols
__global__ void build_W_kernel(const float* __restrict__ Wm,
                               const float* __restrict__ mask,
                               const float* __restrict__ Wa,
                               const float* __restrict__ am,
                               const float* __restrict__ Wc) {
    const int F4 = NPAD / 4;                    // 5008
    int idx = blockIdx.x * blockDim.x + threadIdx.x;
    int total = KDIM * F4;
    if (idx >= total) return;
    int k  = idx / F4;
    int c4 = idx - k * F4;
    int n  = c4 * 4;
    float4 v;
    if (n >= NDIM) {
        v = make_float4(0.f, 0.f, 0.f, 0.f);
    } else if (k < NPROW) {
        float4 w = *reinterpret_cast<const float4*>(Wm + (size_t)k * NDIM + n);
        float4 m = *reinterpret_cast<const float4*>(mask + (size_t)k * NDIM + n);
        v = make_float4(w.x * m.x, w.y * m.y, w.z * m.z, w.w * m.w);
    } else if (k < NPROW + NAROW) {
        int kk = k - NPROW;
        float4 w = *reinterpret_cast<const float4*>(Wa + (size_t)kk * NDIM + n);
        float4 m = *reinterpret_cast<const float4*>(am + (size_t)kk * NDIM + n);
        v = make_float4(w.x * m.x, w.y * m.y, w.z * m.z, w.w * m.w);
    } else {
        int kk = k - NPROW - NAROW;
        v = *reinterpret_cast<const float4*>(Wc + (size_t)kk * NDIM + n);
    }
    reinterpret_cast<float4*>(g_W)[idx] = v;
}

// ---------------------------------------------------------------------------
// GEMM (tf32 wmma) with exp() epilogue. Writes exp(logits) into out (scratch).
__global__ __launch_bounds__(256, 2)
void gemm_exp_kernel(float* __restrict__ out) {
    __shared__ float sm[12288];                 // 48 KB
    float* As = sm;                             // 2 x [128*32]
    float* Bs = sm + 8192;                      // 2 x [32*64]

    // L2-friendly block swizzle (group 16 m-blocks)
    const int g   = 16;
    const int pig = g * GN;
    int bid   = blockIdx.x;
    int group = bid / pig;
    int fm    = group * g;
    int gsz   = min(g, GM - fm);
    int pm    = fm + (bid % gsz);
    int pn    = (bid % pig) / gsz;
    int m0 = pm * BM, n0 = pn * BN;

    int tid  = threadIdx.x;
    int warp = tid >> 5;
    int wm   = warp >> 1;                       // 0..3
    int wn   = warp & 1;                        // 0..1

    wmma::fragment<wmma::accumulator, 16, 16, 8, float> acc[2][2];
#pragma unroll
    for (int i = 0; i < 2; i++)
#pragma unroll
        for (int j = 0; j < 2; j++)
            wmma::fill_fragment(acc[i][j], 0.0f);

    const float* Ag = g_A + (size_t)m0 * KDIM;
    const float* Wg = g_W + n0;

    float4 ra[4], rb[2];

    // prefetch tile 0
    {
        int k0 = 0;
#pragma unroll
        for (int i = 0; i < 4; i++) {
            int idx = tid + i * 256; int r = idx >> 3; int c4 = idx & 7;
            ra[i] = *reinterpret_cast<const float4*>(Ag + (size_t)r * KDIM + k0 + c4 * 4);
        }
#pragma unroll
        for (int i = 0; i < 2; i++) {
            int idx = tid + i * 256; int r = idx >> 4; int c4 = idx & 15;
            rb[i] = *reinterpret_cast<const float4*>(Wg + (size_t)(k0 + r) * NPAD + c4 * 4);
        }
        float* A = As; float* Bb = Bs;
#pragma unroll
        for (int i = 0; i < 4; i++) {
            int idx = tid + i * 256; int r = idx >> 3; int c4 = idx & 7;
            *reinterpret_cast<float4*>(A + r * 32 + c4 * 4) = ra[i];
        }
#pragma unroll
        for (int i = 0; i < 2; i++) {
            int idx = tid + i * 256; int r = idx >> 4; int c4 = idx & 15;
            *reinterpret_cast<float4*>(Bb + r * 64 + c4 * 4) = rb[i];
        }
    }
    __syncthreads();

    for (int kt = 0; kt < NKT; kt++) {
        int buf = kt & 1;
        if (kt + 1 < NKT) {
            int k0 = (kt + 1) * BK;
#pragma unroll
            for (int i = 0; i < 4; i++) {
                int idx = tid + i * 256; int r = idx >> 3; int c4 = idx & 7;
                ra[i] = *reinterpret_cast<const float4*>(Ag + (size_t)r * KDIM + k0 + c4 * 4);
            }
#pragma unroll
            for (int i = 0; i < 2; i++) {
                int idx = tid + i * 256; int r = idx >> 4; int c4 = idx & 15;
                rb[i] = *reinterpret_cast<const float4*>(Wg + (size_t)(k0 + r) * NPAD + c4 * 4);
            }
        }

        const float* A  = As + buf * 4096;
        const float* Bb = Bs + buf * 2048;
#pragma unroll
        for (int kk = 0; kk < BK; kk += 8) {
            wmma::fragment<wmma::matrix_a, 16, 16, 8, wmma::precision::tf32, wmma::row_major> af[2];
            wmma::fragment<wmma::matrix_b, 16, 16, 8, wmma::precision::tf32, wmma::row_major> bf[2];
#pragma unroll
            for (int i = 0; i < 2; i++) {
                wmma::load_matrix_sync(af[i], A + (wm * 32 + i * 16) * 32 + kk, 32);
#pragma unroll
                for (int t = 0; t < af[i].num_elements; t++)
                    af[i].x[t] = wmma::__float_to_tf32(af[i].x[t]);
                wmma::load_matrix_sync(bf[i], Bb + kk * 64 + wn * 32 + i * 16, 64);
#pragma unroll
                for (int t = 0; t < bf[i].num_elements; t++)
                    bf[i].x[t] = wmma::__float_to_tf32(bf[i].x[t]);
            }
#pragma unroll
            for (int i = 0; i < 2; i++)
#pragma unroll
                for (int j = 0; j < 2; j++)
                    wmma::mma_sync(acc[i][j], af[i], bf[j], acc[i][j]);
        }

        if (kt + 1 < NKT) {
            int nbuf = (kt + 1) & 1;
            float* A2 = As + nbuf * 4096; float* B2 = Bs + nbuf * 2048;
#pragma unroll
            for (int i = 0; i < 4; i++) {
                int idx = tid + i * 256; int r = idx >> 3; int c4 = idx & 7;
                *reinterpret_cast<float4*>(A2 + r * 32 + c4 * 4) = ra[i];
            }
#pragma unroll
            for (int i = 0; i < 2; i++) {
                int idx = tid + i * 256; int r = idx >> 4; int c4 = idx & 15;
                *reinterpret_cast<float4*>(B2 + r * 64 + c4 * 4) = rb[i];
            }
        }
        __syncthreads();
    }

    // epilogue: exp() then stage -> guarded coalesced store
    float* stage = sm;                          // [128][68]
#pragma unroll
    for (int i = 0; i < 2; i++)
#pragma unroll
        for (int j = 0; j < 2; j++) {
#pragma unroll
            for (int t = 0; t < acc[i][j].num_elements; t++)
                acc[i][j].x[t] = expf(acc[i][j].x[t]);
            wmma::store_matrix_sync(stage + (wm * 32 + i * 16) * 68 + wn * 32 + j * 16,
                                    acc[i][j], 68, wmma::mem_row_major);
        }
    __syncthreads();
    for (int idx = tid; idx < BM * BN; idx += 256) {
        int r = idx >> 6, c = idx & 63;
        int n = n0 + c;
        if (n < NDIM)
            out[(size_t)(m0 + r) * NDIM + n] = stage[r * 68 + c];
    }
}

// ---------------------------------------------------------------------------
// Per-row sum of exp(logits); scale = exp(log_lib)/sum
__global__ void rowsum_kernel(const float* __restrict__ out,
                              const float* __restrict__ loglib) {
    int row = blockIdx.x;
    const float4* p = reinterpret_cast<const float4*>(out + (size_t)row * NDIM);
    float s = 0.f;
    for (int i = threadIdx.x; i < NDIM / 4; i += blockDim.x) {
        float4 v = p[i];
        s += v.x + v.y + v.z + v.w;
    }
#pragma unroll
    for (int o = 16; o > 0; o >>= 1) s += __shfl_down_sync(0xffffffffu, s, o);
    __shared__ float red[8];
    int lane = threadIdx.x & 31, warp = threadIdx.x >> 5;
    if (lane == 0) red[warp] = s;
    __syncthreads();
    if (warp == 0) {
        float t = (lane < 8) ? red[lane] : 0.f;
#pragma unroll
        for (int o = 4; o > 0; o >>= 1) t += __shfl_down_sync(0xffffffffu, t, o);
        if (lane == 0) g_scale[row] = expf(loglib[row]) / t;
    }
}

// Final in-place scaling
__global__ void scale_kernel(float* __restrict__ out) {
    const int RF4 = NDIM / 4;                   // 5000
    long i = (long)blockIdx.x * blockDim.x + threadIdx.x;
    const long total = (long)BDIM * RF4;
    if (i >= total) return;
    int row = (int)(i / RF4);
    float s = g_scale[row];
    float4 v = reinterpret_cast<float4*>(out)[i];
    v.x *= s; v.y *= s; v.z *= s; v.w *= s;
    reinterpret_cast<float4*>(out)[i] = v;
}

// ---------------------------------------------------------------------------
extern "C" void kernel_launch(void* const* d_in, const int* in_sizes, int n_in,
                              void* d_out, int out_size) {
    const float* z      = (const float*)d_in[0];
    const float* loglib = (const float*)d_in[1];
    const float* cov    = (const float*)d_in[2];
    const float* mask   = (const float*)d_in[3];
    const float* amask  = (const float*)d_in[4];
    const float* Wm     = (const float*)d_in[5];
    const float* Wa     = (const float*)d_in[6];
    const float* Wc     = (const float*)d_in[7];
    float* out = (float*)d_out;

    {
        int total = BDIM * (KDIM / 4);
        build_A_kernel<<<(total + 255) / 256, 256>>>(z, cov);
    }
    {
        int total = KDIM * (NPAD / 4);
        build_W_kernel<<<(total + 255) / 256, 256>>>(Wm, mask, Wa, amask, Wc);
    }
    gemm_exp_kernel<<<GM * GN, 256>>>(out);
    rowsum_kernel<<<BDIM, 256>>>(out, loglib);
    {
        long total = (long)BDIM * (NDIM / 4);
        scale_kernel<<<(unsigned)((total + 255) / 256), 256>>>(out);
    }
}

// round 5
// speedup vs baseline: 3.5660x; 3.5660x over previous
#include <cuda_runtime.h>
#include <cstdint>

#define BDIM   8192
#define KDIM   2336
#define NDIM   20000
#define NPAD   20224   // 79 * 256
#define ZW     2304
#define NPROW  2048
#define NAROW  256
#define NCROW  32

#define BM     128
#define BN     256
#define BK     16
#define NKT    146     // KDIM / BK
#define STAGES 5
#define GRID_M 64      // 8192/128
#define GRID_N 79      // 20224/256
#define GROUP  16

#define ASTR   20      // A smem row stride (floats): conflict-free for frag pattern
#define BSTR   264     // B smem row stride (floats): conflict-free for frag pattern
#define SA_FLOATS (BM * ASTR)            // 2560
#define SB_FLOATS (BK * BSTR)            // 4224
#define STAGE_FLOATS (SA_FLOATS + SB_FLOATS)   // 6784
#define SMEM_BYTES (STAGES * STAGE_FLOATS * 4) // 135680
#define SCR_STR 264   // epilogue scratch row stride (reuses pipeline smem)
#define PW      158   // partial-sum width: 79 n-blocks * 2 halves

__device__ float g_A[(size_t)BDIM * KDIM];     // tf32-rounded
__device__ float g_W[(size_t)KDIM * NPAD];     // tf32-rounded, mask fused, zero-pad
__device__ float g_part[(size_t)BDIM * PW];    // per-(row, 128-col block) exp sums
__device__ float g_scale[BDIM];

// ---------------------------------------------------------------------------
__device__ __forceinline__ uint32_t smem_u32(const void* p) {
    uint32_t a;
    asm("{ .reg .u64 t; cvta.to.shared.u64 t, %1; cvt.u32.u64 %0, t; }" : "=r"(a) : "l"(p));
    return a;
}
__device__ __forceinline__ void cp16(uint32_t dst, const float* src) {
    asm volatile("cp.async.cg.shared.global [%0], [%1], 16;" :: "r"(dst), "l"(src) : "memory");
}
__device__ __forceinline__ float to_tf32(float x) {
    uint32_t u;
    asm("cvt.rna.tf32.f32 %0, %1;" : "=r"(u) : "f"(x));
    return __uint_as_float(u);
}
__device__ __forceinline__ void mma_tf32(float* d, const uint32_t* a, const uint32_t* b) {
    asm volatile("mma.sync.aligned.m16n8k8.row.col.f32.tf32.tf32.f32 "
                 "{%0,%1,%2,%3}, {%4,%5,%6,%7}, {%8,%9}, {%0,%1,%2,%3};"
                 : "+f"(d[0]), "+f"(d[1]), "+f"(d[2]), "+f"(d[3])
                 : "r"(a[0]), "r"(a[1]), "r"(a[2]), "r"(a[3]), "r"(b[0]), "r"(b[1]));
}

// ---------------------------------------------------------------------------
// Pack A = [z | cov], tf32-rounded
__global__ void build_A_kernel(const float* __restrict__ z, const float* __restrict__ cov) {
    const int F4 = KDIM / 4;
    int idx = blockIdx.x * blockDim.x + threadIdx.x;
    if (idx >= BDIM * F4) return;
    int r = idx / F4, c = (idx - r * F4) * 4;
    float4 v;
    if (c < ZW) v = *reinterpret_cast<const float4*>(z + r * ZW + c);
    else        v = *reinterpret_cast<const float4*>(cov + r * NCROW + (c - ZW));
    v.x = to_tf32(v.x); v.y = to_tf32(v.y); v.z = to_tf32(v.z); v.w = to_tf32(v.w);
    reinterpret_cast<float4*>(g_A)[idx] = v;
}

// Pack B = [W_mask*mask ; W_addon*addon_mask ; W_cov], tf32-rounded, zero-pad
__global__ void build_W_kernel(const float* __restrict__ Wm, const float* __restrict__ mask,
                               const float* __restrict__ Wa, const float* __restrict__ am,
                               const float* __restrict__ Wc) {
    const int F4 = NPAD / 4;
    int idx = blockIdx.x * blockDim.x + threadIdx.x;
    if (idx >= KDIM * F4) return;
    int k = idx / F4, n = (idx - k * F4) * 4;
    float4 v;
    if (n >= NDIM) {
        v = make_float4(0.f, 0.f, 0.f, 0.f);
    } else if (k < NPROW) {
        float4 w = *reinterpret_cast<const float4*>(Wm + (size_t)k * NDIM + n);
        float4 m = *reinterpret_cast<const float4*>(mask + (size_t)k * NDIM + n);
        v = make_float4(w.x * m.x, w.y * m.y, w.z * m.z, w.w * m.w);
    } else if (k < NPROW + NAROW) {
        int kk = k - NPROW;
        float4 w = *reinterpret_cast<const float4*>(Wa + (size_t)kk * NDIM + n);
        float4 m = *reinterpret_cast<const float4*>(am + (size_t)kk * NDIM + n);
        v = make_float4(w.x * m.x, w.y * m.y, w.z * m.z, w.w * m.w);
    } else {
        int kk = k - NPROW - NAROW;
        v = *reinterpret_cast<const float4*>(Wc + (size_t)kk * NDIM + n);
    }
    v.x = to_tf32(v.x); v.y = to_tf32(v.y); v.z = to_tf32(v.z); v.w = to_tf32(v.w);
    reinterpret_cast<float4*>(g_W)[idx] = v;
}

// ---------------------------------------------------------------------------
// 128x256 CTA, 8 warps of 64x64, tf32 mma.sync, 5-stage cp.async pipeline.
// Epilogue: exp(), coalesced store, fused per-row partial sums.
__global__ __launch_bounds__(256, 1)
void gemm_exp_kernel(float* __restrict__ out) {
    extern __shared__ float sm[];
    const int t   = threadIdx.x;
    const int wid = t >> 5;
    const int lid = t & 31;
    const int g   = lid >> 2;     // 0..7
    const int tig = lid & 3;      // 0..3

    // L2-friendly swizzle: groups of 16 m-blocks share B
    const int per = GROUP * GRID_N;
    int bid = blockIdx.x;
    int grp = bid / per;
    int loc = bid - grp * per;
    int pm  = grp * GROUP + (loc & (GROUP - 1));
    int pn  = loc >> 4;           // GROUP == 16
    const int m0 = pm * BM;
    const int n0 = pn * BN;

    const int wm = wid >> 2;      // 0..1
    const int wn = wid & 3;       // 0..3
    const int mbase = wm * 64;
    const int nbase = wn * 64;

    float acc[4][8][4];
#pragma unroll
    for (int i = 0; i < 4; i++)
#pragma unroll
        for (int j = 0; j < 8; j++)
#pragma unroll
            for (int q = 0; q < 4; q++) acc[i][j][q] = 0.f;

    const uint32_t smb = smem_u32(sm);

    // --- stage loader (all 256 threads) ---
    auto load_stage = [&](int slot, int ks) {
        const int k0 = ks * BK;
        const uint32_t sa = smb + (slot * STAGE_FLOATS) * 4;
        const uint32_t sb = sa + SA_FLOATS * 4;
        // A: 512 x 16B   (r = chunk>>2, c4 = chunk&3)
#pragma unroll
        for (int j = 0; j < 2; j++) {
            int i = t + j * 256;
            int r = i >> 2, c4 = i & 3;
            cp16(sa + (r * ASTR + c4 * 4) * 4, g_A + (size_t)(m0 + r) * KDIM + k0 + c4 * 4);
        }
        // B: 1024 x 16B  (k = chunk>>6, c4 = chunk&63)
#pragma unroll
        for (int j = 0; j < 4; j++) {
            int i = t + j * 256;
            int k = i >> 6, c4 = i & 63;
            cp16(sb + (k * BSTR + c4 * 4) * 4, g_W + (size_t)(k0 + k) * NPAD + n0 + c4 * 4);
        }
    };

    // prologue: stages 0..3
#pragma unroll
    for (int s = 0; s < STAGES - 1; s++) {
        load_stage(s, s);
        asm volatile("cp.async.commit_group;" ::: "memory");
    }

    for (int kt = 0; kt < NKT; kt++) {
        asm volatile("cp.async.wait_group %0;" :: "n"(STAGES - 2) : "memory");
        __syncthreads();

        // issue stage kt+4 (overwrites slot computed at kt-1)
        int ks = kt + STAGES - 1;
        if (ks < NKT) load_stage(ks % STAGES, ks);
        asm volatile("cp.async.commit_group;" ::: "memory");

        const int slot = kt % STAGES;
        const float* sA = sm + slot * STAGE_FLOATS;
        const float* sB = sA + SA_FLOATS;

#pragma unroll
        for (int kk = 0; kk < BK; kk += 8) {
            uint32_t af[4][4], bf[8][2];
#pragma unroll
            for (int mf = 0; mf < 4; mf++) {
                int r0 = mbase + mf * 16 + g;
                af[mf][0] = __float_as_uint(sA[(r0)     * ASTR + kk + tig]);
                af[mf][1] = __float_as_uint(sA[(r0 + 8) * ASTR + kk + tig]);
                af[mf][2] = __float_as_uint(sA[(r0)     * ASTR + kk + tig + 4]);
                af[mf][3] = __float_as_uint(sA[(r0 + 8) * ASTR + kk + tig + 4]);
            }
#pragma unroll
            for (int nf = 0; nf < 8; nf++) {
                int c0 = nbase + nf * 8 + g;
                bf[nf][0] = __float_as_uint(sB[(kk + tig)     * BSTR + c0]);
                bf[nf][1] = __float_as_uint(sB[(kk + tig + 4) * BSTR + c0]);
            }
#pragma unroll
            for (int mf = 0; mf < 4; mf++)
#pragma unroll
                for (int nf = 0; nf < 8; nf++)
                    mma_tf32(acc[mf][nf], af[mf], bf[nf]);
        }
        __syncthreads();
    }

    asm volatile("cp.async.wait_group 0;" ::: "memory");
    __syncthreads();

    // ---- epilogue: exp -> smem scratch [128][264] ----
    float* sc = sm;
#pragma unroll
    for (int mf = 0; mf < 4; mf++) {
        int r0 = mbase + mf * 16 + g;
#pragma unroll
        for (int nf = 0; nf < 8; nf++) {
            int c0 = nbase + nf * 8 + tig * 2;
            sc[(r0)     * SCR_STR + c0]     = __expf(acc[mf][nf][0]);
            sc[(r0)     * SCR_STR + c0 + 1] = __expf(acc[mf][nf][1]);
            sc[(r0 + 8) * SCR_STR + c0]     = __expf(acc[mf][nf][2]);
            sc[(r0 + 8) * SCR_STR + c0 + 1] = __expf(acc[mf][nf][3]);
        }
    }
    __syncthreads();

    // coalesced store + fused row partial sums (per warp: one row, 128 cols/iter)
#pragma unroll 4
    for (int it = 0; it < 32; it++) {
        int idx = it * 256 + t;
        int r   = idx >> 6;          // 0..127 (constant within warp)
        int c4  = idx & 63;          // 0..63
        int n   = n0 + c4 * 4;
        float4 v;
        float s;
        bool valid = (n < NDIM);
        if (valid) {
            v = *reinterpret_cast<const float4*>(sc + r * SCR_STR + c4 * 4);
            s = v.x + v.y + v.z + v.w;
        } else {
            s = 0.f;
        }
        if (valid)
            *reinterpret_cast<float4*>(out + (size_t)(m0 + r) * NDIM + n) = v;
#pragma unroll
        for (int o = 16; o > 0; o >>= 1) s += __shfl_down_sync(0xffffffffu, s, o);
        if (lid == 0) {
            int half = (c4 >> 5);    // 0 or 1
            g_part[(size_t)(m0 + r) * PW + pn * 2 + half] = s;
        }
    }
}

// ---------------------------------------------------------------------------
__global__ void reduce_kernel(const float* __restrict__ loglib) {
    int row = blockIdx.x;
    float s = 0.f;
    for (int i = threadIdx.x; i < PW; i += 32) s += g_part[(size_t)row * PW + i];
#pragma unroll
    for (int o = 16; o > 0; o >>= 1) s += __shfl_down_sync(0xffffffffu, s, o);
    if (threadIdx.x == 0) g_scale[row] = expf(loglib[row]) / s;
}

__global__ void scale_kernel(float* __restrict__ out) {
    const int RF4 = NDIM / 4;
    long i = (long)blockIdx.x * blockDim.x + threadIdx.x;
    if (i >= (long)BDIM * RF4) return;
    int row = (int)(i / RF4);
    float s = g_scale[row];
    float4 v = reinterpret_cast<float4*>(out)[i];
    v.x *= s; v.y *= s; v.z *= s; v.w *= s;
    reinterpret_cast<float4*>(out)[i] = v;
}

// ---------------------------------------------------------------------------
extern "C" void kernel_launch(void* const* d_in, const int* in_sizes, int n_in,
                              void* d_out, int out_size) {
    const float* z      = (const float*)d_in[0];
    const float* loglib = (const float*)d_in[1];
    const float* cov    = (const float*)d_in[2];
    const float* mask   = (const float*)d_in[3];
    const float* amask  = (const float*)d_in[4];
    const float* Wm     = (const float*)d_in[5];
    const float* Wa     = (const float*)d_in[6];
    const float* Wc     = (const float*)d_in[7];
    float* out = (float*)d_out;

    cudaFuncSetAttribute(gemm_exp_kernel, cudaFuncAttributeMaxDynamicSharedMemorySize, SMEM_BYTES);

    {
        int total = BDIM * (KDIM / 4);
        build_A_kernel<<<(total + 255) / 256, 256>>>(z, cov);
    }
    {
        int total = KDIM * (NPAD / 4);
        build_W_kernel<<<(total + 255) / 256, 256>>>(Wm, mask, Wa, amask, Wc);
    }
    gemm_exp_kernel<<<GRID_M * GRID_N, 256, SMEM_BYTES>>>(out);
    reduce_kernel<<<BDIM, 32>>>(loglib);
    {
        long total = (long)BDIM * (NDIM / 4);
        scale_kernel<<<(unsigned)((total + 255) / 256), 256>>>(out);
    }
}

// round 6
// speedup vs baseline: 6.4081x; 1.7970x over previous
#include <cuda_runtime.h>
#include <cuda_fp16.h>
#include <cstdint>

#define BDIM   8192
#define KDIM   2336
#define NDIM   20000
#define NPAD   20224   // 79 * 256
#define ZW     2304
#define NPROW  2048
#define NAROW  256
#define NCROW  32

#define BM     128
#define BN     256
#define BK     32
#define NKT    73      // KDIM / BK
#define STAGES 6
#define GRID_M 64
#define GRID_N 79
#define GROUP  16

#define ASTRB  80      // A smem row stride bytes (5*16 -> conflict-free ldmatrix)
#define BSTRB  528     // B smem row stride bytes (33*16 -> conflict-free ldmatrix)
#define STAGE_BYTES (BM * ASTRB + BK * BSTRB)      // 10240 + 16896 = 27136
#define SMEM_BYTES  (STAGES * STAGE_BYTES)         // 162816
#define SCR_STR 132   // epilogue scratch stride (floats), half-tile 128 cols
#define PW      158   // 79 n-blocks * 2 halves

__device__ __align__(16) __half g_Ah[(size_t)BDIM * KDIM];
__device__ __align__(16) __half g_Wh[(size_t)KDIM * NPAD];
__device__ float g_part[(size_t)BDIM * PW];
__device__ float g_scale[BDIM];

// ---------------------------------------------------------------------------
__device__ __forceinline__ uint32_t smem_u32(const void* p) {
    uint32_t a;
    asm("{ .reg .u64 t; cvta.to.shared.u64 t, %1; cvt.u32.u64 %0, t; }" : "=r"(a) : "l"(p));
    return a;
}
__device__ __forceinline__ void cp16(uint32_t dst, const void* src) {
    asm volatile("cp.async.cg.shared.global [%0], [%1], 16;" :: "r"(dst), "l"(src) : "memory");
}
__device__ __forceinline__ void ldsm_x4(uint32_t* r, uint32_t addr) {
    asm volatile("ldmatrix.sync.aligned.m8n8.x4.shared.b16 {%0,%1,%2,%3}, [%4];"
                 : "=r"(r[0]), "=r"(r[1]), "=r"(r[2]), "=r"(r[3]) : "r"(addr));
}
__device__ __forceinline__ void ldsm_x4_t(uint32_t* r, uint32_t addr) {
    asm volatile("ldmatrix.sync.aligned.m8n8.x4.trans.shared.b16 {%0,%1,%2,%3}, [%4];"
                 : "=r"(r[0]), "=r"(r[1]), "=r"(r[2]), "=r"(r[3]) : "r"(addr));
}
__device__ __forceinline__ void mma_f16(float* d, const uint32_t* a, const uint32_t* b) {
    asm volatile("mma.sync.aligned.m16n8k16.row.col.f32.f16.f16.f32 "
                 "{%0,%1,%2,%3}, {%4,%5,%6,%7}, {%8,%9}, {%0,%1,%2,%3};"
                 : "+f"(d[0]), "+f"(d[1]), "+f"(d[2]), "+f"(d[3])
                 : "r"(a[0]), "r"(a[1]), "r"(a[2]), "r"(a[3]), "r"(b[0]), "r"(b[1]));
}
__device__ __forceinline__ uint32_t pack_h2(float x, float y) {
    __half2 h = __float22half2_rn(make_float2(x, y));
    return *reinterpret_cast<uint32_t*>(&h);
}

// ---------------------------------------------------------------------------
// Pack A = [z | cov] -> fp16, K contiguous. 8 halves per thread.
__global__ void build_A_kernel(const float* __restrict__ z, const float* __restrict__ cov) {
    const int F8 = KDIM / 8;                  // 292
    int idx = blockIdx.x * blockDim.x + threadIdx.x;
    if (idx >= BDIM * F8) return;
    int r = idx / F8, c = (idx - r * F8) * 8;
    float4 v0, v1;
    if (c < ZW) {
        v0 = *reinterpret_cast<const float4*>(z + (size_t)r * ZW + c);
        v1 = *reinterpret_cast<const float4*>(z + (size_t)r * ZW + c + 4);
    } else {
        v0 = *reinterpret_cast<const float4*>(cov + (size_t)r * NCROW + (c - ZW));
        v1 = *reinterpret_cast<const float4*>(cov + (size_t)r * NCROW + (c - ZW) + 4);
    }
    uint4 o;
    o.x = pack_h2(v0.x, v0.y); o.y = pack_h2(v0.z, v0.w);
    o.z = pack_h2(v1.x, v1.y); o.w = pack_h2(v1.z, v1.w);
    reinterpret_cast<uint4*>(g_Ah)[idx] = o;
}

// Pack B = [W_mask*mask ; W_addon*am ; W_cov] -> fp16, zero-pad cols
__global__ void build_W_kernel(const float* __restrict__ Wm, const float* __restrict__ mask,
                               const float* __restrict__ Wa, const float* __restrict__ am,
                               const float* __restrict__ Wc) {
    const int F8 = NPAD / 8;                  // 2528
    int idx = blockIdx.x * blockDim.x + threadIdx.x;
    if (idx >= KDIM * F8) return;
    int k = idx / F8, n = (idx - k * F8) * 8;
    float4 v0, v1;
    if (n >= NDIM) {
        v0 = make_float4(0.f, 0.f, 0.f, 0.f); v1 = v0;
    } else if (k < NPROW) {
        float4 w0 = *reinterpret_cast<const float4*>(Wm + (size_t)k * NDIM + n);
        float4 w1 = *reinterpret_cast<const float4*>(Wm + (size_t)k * NDIM + n + 4);
        float4 m0 = *reinterpret_cast<const float4*>(mask + (size_t)k * NDIM + n);
        float4 m1 = *reinterpret_cast<const float4*>(mask + (size_t)k * NDIM + n + 4);
        v0 = make_float4(w0.x * m0.x, w0.y * m0.y, w0.z * m0.z, w0.w * m0.w);
        v1 = make_float4(w1.x * m1.x, w1.y * m1.y, w1.z * m1.z, w1.w * m1.w);
    } else if (k < NPROW + NAROW) {
        int kk = k - NPROW;
        float4 w0 = *reinterpret_cast<const float4*>(Wa + (size_t)kk * NDIM + n);
        float4 w1 = *reinterpret_cast<const float4*>(Wa + (size_t)kk * NDIM + n + 4);
        float4 m0 = *reinterpret_cast<const float4*>(am + (size_t)kk * NDIM + n);
        float4 m1 = *reinterpret_cast<const float4*>(am + (size_t)kk * NDIM + n + 4);
        v0 = make_float4(w0.x * m0.x, w0.y * m0.y, w0.z * m0.z, w0.w * m0.w);
        v1 = make_float4(w1.x * m1.x, w1.y * m1.y, w1.z * m1.z, w1.w * m1.w);
    } else {
        int kk = k - NPROW - NAROW;
        v0 = *reinterpret_cast<const float4*>(Wc + (size_t)kk * NDIM + n);
        v1 = *reinterpret_cast<const float4*>(Wc + (size_t)kk * NDIM + n + 4);
    }
    uint4 o;
    o.x = pack_h2(v0.x, v0.y); o.y = pack_h2(v0.z, v0.w);
    o.z = pack_h2(v1.x, v1.y); o.w = pack_h2(v1.z, v1.w);
    reinterpret_cast<uint4*>(g_Wh)[idx] = o;
}

// ---------------------------------------------------------------------------
// fp16 mma.sync GEMM 128x256 CTA / 64x64 warp, ldmatrix frags, 6-stage cp.async.
__global__ __launch_bounds__(256, 1)
void gemm_exp_kernel(float* __restrict__ out) {
    extern __shared__ float sm[];
    const int t   = threadIdx.x;
    const int wid = t >> 5;
    const int lid = t & 31;
    const int g   = lid >> 2;
    const int tig = lid & 3;

    const int per = GROUP * GRID_N;
    int bid = blockIdx.x;
    int grp = bid / per;
    int loc = bid - grp * per;
    int pm  = grp * GROUP + (loc & (GROUP - 1));
    int pn  = loc >> 4;
    const int m0 = pm * BM;
    const int n0 = pn * BN;

    const int wm = wid >> 2;
    const int wn = wid & 3;
    const int mbase = wm * 64;
    const int nbase = wn * 64;

    float acc[4][8][4];
#pragma unroll
    for (int i = 0; i < 4; i++)
#pragma unroll
        for (int j = 0; j < 8; j++)
#pragma unroll
            for (int q = 0; q < 4; q++) acc[i][j][q] = 0.f;

    const uint32_t smb = smem_u32(sm);

    // ldmatrix per-lane address components
    const int laneRow = (lid & 7) + ((lid >> 3) & 1) * 8;   // 0..15
    const int laneHi  = (lid >> 4);                          // 0 or 1
    const uint32_t offA = (uint32_t)(mbase + laneRow) * ASTRB + laneHi * 16;
    const uint32_t offB = (uint32_t)laneRow * BSTRB + (uint32_t)(nbase + laneHi * 8) * 2;

    auto load_stage = [&](int slot, int ks) {
        const int k0 = ks * BK;
        const uint32_t sa = smb + slot * STAGE_BYTES;
        const uint32_t sb = sa + BM * ASTRB;
        // A: 512 chunks of 16B (8 halves)
#pragma unroll
        for (int j = 0; j < 2; j++) {
            int i = t + j * 256;
            int r = i >> 2, c = i & 3;
            cp16(sa + r * ASTRB + c * 16, g_Ah + (size_t)(m0 + r) * KDIM + k0 + c * 8);
        }
        // B: 1024 chunks of 16B
#pragma unroll
        for (int j = 0; j < 4; j++) {
            int i = t + j * 256;
            int k = i >> 5, c = i & 31;
            cp16(sb + k * BSTRB + c * 16, g_Wh + (size_t)(k0 + k) * NPAD + n0 + c * 8);
        }
    };

#pragma unroll
    for (int s = 0; s < STAGES - 1; s++) {
        load_stage(s, s);
        asm volatile("cp.async.commit_group;" ::: "memory");
    }

    for (int kt = 0; kt < NKT; kt++) {
        asm volatile("cp.async.wait_group %0;" :: "n"(STAGES - 2) : "memory");
        __syncthreads();

        int ks = kt + STAGES - 1;
        if (ks < NKT) load_stage(ks % STAGES, ks);
        asm volatile("cp.async.commit_group;" ::: "memory");

        const int slot = kt % STAGES;
        const uint32_t sa = smb + slot * STAGE_BYTES;
        const uint32_t sb = sa + BM * ASTRB;
        const uint32_t pA = sa + offA;
        const uint32_t pB = sb + offB;

#pragma unroll
        for (int kk = 0; kk < BK; kk += 16) {
            uint32_t af[4][4], bf[8][2];
#pragma unroll
            for (int mf = 0; mf < 4; mf++)
                ldsm_x4(af[mf], pA + mf * (16 * ASTRB) + kk * 2);
#pragma unroll
            for (int nf2 = 0; nf2 < 4; nf2++) {
                uint32_t r[4];
                ldsm_x4_t(r, pB + kk * BSTRB + nf2 * 32);
                bf[nf2 * 2][0]     = r[0]; bf[nf2 * 2][1]     = r[1];
                bf[nf2 * 2 + 1][0] = r[2]; bf[nf2 * 2 + 1][1] = r[3];
            }
#pragma unroll
            for (int mf = 0; mf < 4; mf++)
#pragma unroll
                for (int nf = 0; nf < 8; nf++)
                    mma_f16(acc[mf][nf], af[mf], bf[nf]);
        }
        __syncthreads();
    }

    asm volatile("cp.async.wait_group 0;" ::: "memory");
    __syncthreads();

    // ---- epilogue in two 128-col halves: exp -> scratch -> store + partials ----
    float* sc = sm;
#pragma unroll
    for (int h = 0; h < 2; h++) {
        if ((wn >> 1) == h) {
            const int cb = nbase - h * 128;
#pragma unroll
            for (int mf = 0; mf < 4; mf++) {
                int r0 = mbase + mf * 16 + g;
#pragma unroll
                for (int nf = 0; nf < 8; nf++) {
                    int c0 = cb + nf * 8 + tig * 2;
                    sc[(r0)     * SCR_STR + c0]     = __expf(acc[mf][nf][0]);
                    sc[(r0)     * SCR_STR + c0 + 1] = __expf(acc[mf][nf][1]);
                    sc[(r0 + 8) * SCR_STR + c0]     = __expf(acc[mf][nf][2]);
                    sc[(r0 + 8) * SCR_STR + c0 + 1] = __expf(acc[mf][nf][3]);
                }
            }
        }
        __syncthreads();
#pragma unroll 4
        for (int it = 0; it < 16; it++) {
            int idx = it * 256 + t;
            int r   = idx >> 5;            // row 0..127 (constant per warp)
            int c4  = idx & 31;            // 0..31 float4 within half
            int n   = n0 + h * 128 + c4 * 4;
            float4 v; float s;
            bool valid = (n < NDIM);
            if (valid) {
                v = *reinterpret_cast<const float4*>(sc + r * SCR_STR + c4 * 4);
                s = v.x + v.y + v.z + v.w;
                *reinterpret_cast<float4*>(out + (size_t)(m0 + r) * NDIM + n) = v;
            } else s = 0.f;
#pragma unroll
            for (int o = 16; o > 0; o >>= 1) s += __shfl_down_sync(0xffffffffu, s, o);
            if (lid == 0)
                g_part[(size_t)(m0 + r) * PW + pn * 2 + h] = s;
        }
        __syncthreads();
    }
}

// ---------------------------------------------------------------------------
__global__ void reduce_kernel(const float* __restrict__ loglib) {
    int row = blockIdx.x;
    float s = 0.f;
    for (int i = threadIdx.x; i < PW; i += 32) s += g_part[(size_t)row * PW + i];
#pragma unroll
    for (int o = 16; o > 0; o >>= 1) s += __shfl_down_sync(0xffffffffu, s, o);
    if (threadIdx.x == 0) g_scale[row] = expf(loglib[row]) / s;
}

__global__ void scale_kernel(float* __restrict__ out) {
    const int RF4 = NDIM / 4;
    long i = (long)blockIdx.x * blockDim.x + threadIdx.x;
    if (i >= (long)BDIM * RF4) return;
    int row = (int)(i / RF4);
    float s = g_scale[row];
    float4 v = reinterpret_cast<float4*>(out)[i];
    v.x *= s; v.y *= s; v.z *= s; v.w *= s;
    reinterpret_cast<float4*>(out)[i] = v;
}

// ---------------------------------------------------------------------------
extern "C" void kernel_launch(void* const* d_in, const int* in_sizes, int n_in,
                              void* d_out, int out_size) {
    const float* z      = (const float*)d_in[0];
    const float* loglib = (const float*)d_in[1];
    const float* cov    = (const float*)d_in[2];
    const float* mask   = (const float*)d_in[3];
    const float* amask  = (const float*)d_in[4];
    const float* Wm     = (const float*)d_in[5];
    const float* Wa     = (const float*)d_in[6];
    const float* Wc     = (const float*)d_in[7];
    float* out = (float*)d_out;

    cudaFuncSetAttribute(gemm_exp_kernel, cudaFuncAttributeMaxDynamicSharedMemorySize, SMEM_BYTES);

    {
        int total = BDIM * (KDIM / 8);
        build_A_kernel<<<(total + 255) / 256, 256>>>(z, cov);
    }
    {
        int total = KDIM * (NPAD / 8);
        build_W_kernel<<<(total + 255) / 256, 256>>>(Wm, mask, Wa, amask, Wc);
    }
    gemm_exp_kernel<<<GRID_M * GRID_N, 256, SMEM_BYTES>>>(out);
    reduce_kernel<<<BDIM, 32>>>(loglib);
    {
        long total = (long)BDIM * (NDIM / 4);
        scale_kernel<<<(unsigned)((total + 255) / 256), 256>>>(out);
    }
}

// round 7
// speedup vs baseline: 6.4084x; 1.0000x over previous
#include <cuda_runtime.h>
#include <cuda_fp16.h>
#include <cstdint>

#define BDIM   8192
#define KDIM   2336
#define NDIM   20000
#define NPAD   20224   // 79 * 256
#define ZW     2304
#define NPROW  2048
#define NAROW  256
#define NCROW  32

#define BM     128
#define BN     256
#define BK     32
#define NKT    73      // KDIM / BK
#define STAGES 6
#define GRID_M 64
#define GRID_N 79
#define GROUP  16

#define NTHR   512     // 16 warps: 2 (m) x 8 (n), 64x32 warp tiles

#define ASTRB  80      // A smem row stride bytes (5*16 -> conflict-free ldmatrix)
#define BSTRB  528     // B smem row stride bytes (33*16 -> conflict-free ldmatrix)
#define STAGE_BYTES (BM * ASTRB + BK * BSTRB)      // 27136
#define SMEM_BYTES  (STAGES * STAGE_BYTES)         // 162816
#define SCR_STR 132
#define PW      158    // 79 n-blocks * 2 halves

__device__ __align__(16) __half g_Ah[(size_t)BDIM * KDIM];
__device__ __align__(16) __half g_Wh[(size_t)KDIM * NPAD];
__device__ float g_part[(size_t)BDIM * PW];
__device__ float g_scale[BDIM];

// ---------------------------------------------------------------------------
__device__ __forceinline__ uint32_t smem_u32(const void* p) {
    uint32_t a;
    asm("{ .reg .u64 t; cvta.to.shared.u64 t, %1; cvt.u32.u64 %0, t; }" : "=r"(a) : "l"(p));
    return a;
}
__device__ __forceinline__ void cp16(uint32_t dst, const void* src) {
    asm volatile("cp.async.cg.shared.global [%0], [%1], 16;" :: "r"(dst), "l"(src) : "memory");
}
__device__ __forceinline__ void ldsm_x4(uint32_t* r, uint32_t addr) {
    asm volatile("ldmatrix.sync.aligned.m8n8.x4.shared.b16 {%0,%1,%2,%3}, [%4];"
                 : "=r"(r[0]), "=r"(r[1]), "=r"(r[2]), "=r"(r[3]) : "r"(addr));
}
__device__ __forceinline__ void ldsm_x4_t(uint32_t* r, uint32_t addr) {
    asm volatile("ldmatrix.sync.aligned.m8n8.x4.trans.shared.b16 {%0,%1,%2,%3}, [%4];"
                 : "=r"(r[0]), "=r"(r[1]), "=r"(r[2]), "=r"(r[3]) : "r"(addr));
}
__device__ __forceinline__ void mma_f16(float* d, const uint32_t* a, const uint32_t* b) {
    asm volatile("mma.sync.aligned.m16n8k16.row.col.f32.f16.f16.f32 "
                 "{%0,%1,%2,%3}, {%4,%5,%6,%7}, {%8,%9}, {%0,%1,%2,%3};"
                 : "+f"(d[0]), "+f"(d[1]), "+f"(d[2]), "+f"(d[3])
                 : "r"(a[0]), "r"(a[1]), "r"(a[2]), "r"(a[3]), "r"(b[0]), "r"(b[1]));
}
__device__ __forceinline__ uint32_t pack_h2(float x, float y) {
    __half2 h = __float22half2_rn(make_float2(x, y));
    return *reinterpret_cast<uint32_t*>(&h);
}

// ---------------------------------------------------------------------------
__global__ void build_A_kernel(const float* __restrict__ z, const float* __restrict__ cov) {
    const int F8 = KDIM / 8;
    int idx = blockIdx.x * blockDim.x + threadIdx.x;
    if (idx >= BDIM * F8) return;
    int r = idx / F8, c = (idx - r * F8) * 8;
    float4 v0, v1;
    if (c < ZW) {
        v0 = *reinterpret_cast<const float4*>(z + (size_t)r * ZW + c);
        v1 = *reinterpret_cast<const float4*>(z + (size_t)r * ZW + c + 4);
    } else {
        v0 = *reinterpret_cast<const float4*>(cov + (size_t)r * NCROW + (c - ZW));
        v1 = *reinterpret_cast<const float4*>(cov + (size_t)r * NCROW + (c - ZW) + 4);
    }
    uint4 o;
    o.x = pack_h2(v0.x, v0.y); o.y = pack_h2(v0.z, v0.w);
    o.z = pack_h2(v1.x, v1.y); o.w = pack_h2(v1.z, v1.w);
    reinterpret_cast<uint4*>(g_Ah)[idx] = o;
}

__global__ void build_W_kernel(const float* __restrict__ Wm, const float* __restrict__ mask,
                               const float* __restrict__ Wa, const float* __restrict__ am,
                               const float* __restrict__ Wc) {
    const int F8 = NPAD / 8;
    int idx = blockIdx.x * blockDim.x + threadIdx.x;
    if (idx >= KDIM * F8) return;
    int k = idx / F8, n = (idx - k * F8) * 8;
    float4 v0, v1;
    if (n >= NDIM) {
        v0 = make_float4(0.f, 0.f, 0.f, 0.f); v1 = v0;
    } else if (k < NPROW) {
        float4 w0 = *reinterpret_cast<const float4*>(Wm + (size_t)k * NDIM + n);
        float4 w1 = *reinterpret_cast<const float4*>(Wm + (size_t)k * NDIM + n + 4);
        float4 m0 = *reinterpret_cast<const float4*>(mask + (size_t)k * NDIM + n);
        float4 m1 = *reinterpret_cast<const float4*>(mask + (size_t)k * NDIM + n + 4);
        v0 = make_float4(w0.x * m0.x, w0.y * m0.y, w0.z * m0.z, w0.w * m0.w);
        v1 = make_float4(w1.x * m1.x, w1.y * m1.y, w1.z * m1.z, w1.w * m1.w);
    } else if (k < NPROW + NAROW) {
        int kk = k - NPROW;
        float4 w0 = *reinterpret_cast<const float4*>(Wa + (size_t)kk * NDIM + n);
        float4 w1 = *reinterpret_cast<const float4*>(Wa + (size_t)kk * NDIM + n + 4);
        float4 m0 = *reinterpret_cast<const float4*>(am + (size_t)kk * NDIM + n);
        float4 m1 = *reinterpret_cast<const float4*>(am + (size_t)kk * NDIM + n + 4);
        v0 = make_float4(w0.x * m0.x, w0.y * m0.y, w0.z * m0.z, w0.w * m0.w);
        v1 = make_float4(w1.x * m1.x, w1.y * m1.y, w1.z * m1.z, w1.w * m1.w);
    } else {
        int kk = k - NPROW - NAROW;
        v0 = *reinterpret_cast<const float4*>(Wc + (size_t)kk * NDIM + n);
        v1 = *reinterpret_cast<const float4*>(Wc + (size_t)kk * NDIM + n + 4);
    }
    uint4 o;
    o.x = pack_h2(v0.x, v0.y); o.y = pack_h2(v0.z, v0.w);
    o.z = pack_h2(v1.x, v1.y); o.w = pack_h2(v1.z, v1.w);
    reinterpret_cast<uint4*>(g_Wh)[idx] = o;
}

// ---------------------------------------------------------------------------
// fp16 mma.sync GEMM: 128x256 CTA, 16 warps (2x8) of 64x32, 6-stage cp.async.
__global__ __launch_bounds__(NTHR, 1)
void gemm_exp_kernel(float* __restrict__ out) {
    extern __shared__ float sm[];
    const int t   = threadIdx.x;
    const int wid = t >> 5;
    const int lid = t & 31;
    const int g   = lid >> 2;
    const int tig = lid & 3;

    const int per = GROUP * GRID_N;
    int bid = blockIdx.x;
    int grp = bid / per;
    int loc = bid - grp * per;
    int pm  = grp * GROUP + (loc & (GROUP - 1));
    int pn  = loc >> 4;
    const int m0 = pm * BM;
    const int n0 = pn * BN;

    const int wm = wid >> 3;      // 0..1
    const int wn = wid & 7;       // 0..7
    const int mbase = wm * 64;
    const int nbase = wn * 32;

    float acc[4][4][4];
#pragma unroll
    for (int i = 0; i < 4; i++)
#pragma unroll
        for (int j = 0; j < 4; j++)
#pragma unroll
            for (int q = 0; q < 4; q++) acc[i][j][q] = 0.f;

    const uint32_t smb = smem_u32(sm);

    const int laneRow = (lid & 7) + ((lid >> 3) & 1) * 8;   // 0..15
    const int laneHi  = (lid >> 4);                          // 0 or 1
    const uint32_t offA = (uint32_t)(mbase + laneRow) * ASTRB + laneHi * 16;
    const uint32_t offB = (uint32_t)laneRow * BSTRB + (uint32_t)(nbase + laneHi * 8) * 2;

    auto load_stage = [&](int slot, int ks) {
        const int k0 = ks * BK;
        const uint32_t sa = smb + slot * STAGE_BYTES;
        const uint32_t sb = sa + BM * ASTRB;
        // A: 512 chunks of 16B — one per thread
        {
            int r = t >> 2, c = t & 3;
            cp16(sa + r * ASTRB + c * 16, g_Ah + (size_t)(m0 + r) * KDIM + k0 + c * 8);
        }
        // B: 1024 chunks of 16B — two per thread
#pragma unroll
        for (int j = 0; j < 2; j++) {
            int i = t + j * NTHR;
            int k = i >> 5, c = i & 31;
            cp16(sb + k * BSTRB + c * 16, g_Wh + (size_t)(k0 + k) * NPAD + n0 + c * 8);
        }
    };

#pragma unroll
    for (int s = 0; s < STAGES - 1; s++) {
        load_stage(s, s);
        asm volatile("cp.async.commit_group;" ::: "memory");
    }

    for (int kt = 0; kt < NKT; kt++) {
        asm volatile("cp.async.wait_group %0;" :: "n"(STAGES - 2) : "memory");
        __syncthreads();

        int ks = kt + STAGES - 1;
        if (ks < NKT) load_stage(ks % STAGES, ks);
        asm volatile("cp.async.commit_group;" ::: "memory");

        const int slot = kt % STAGES;
        const uint32_t sa = smb + slot * STAGE_BYTES;
        const uint32_t sb = sa + BM * ASTRB;
        const uint32_t pA = sa + offA;
        const uint32_t pB = sb + offB;

#pragma unroll
        for (int kk = 0; kk < BK; kk += 16) {
            uint32_t af[4][4], bf[4][2];
#pragma unroll
            for (int mf = 0; mf < 4; mf++)
                ldsm_x4(af[mf], pA + mf * (16 * ASTRB) + kk * 2);
#pragma unroll
            for (int nf2 = 0; nf2 < 2; nf2++) {
                uint32_t r[4];
                ldsm_x4_t(r, pB + kk * BSTRB + nf2 * 32);
                bf[nf2 * 2][0]     = r[0]; bf[nf2 * 2][1]     = r[1];
                bf[nf2 * 2 + 1][0] = r[2]; bf[nf2 * 2 + 1][1] = r[3];
            }
#pragma unroll
            for (int mf = 0; mf < 4; mf++)
#pragma unroll
                for (int nf = 0; nf < 4; nf++)
                    mma_f16(acc[mf][nf], af[mf], bf[nf]);
        }
        __syncthreads();
    }

    asm volatile("cp.async.wait_group 0;" ::: "memory");
    __syncthreads();

    // ---- epilogue in two 128-col halves ----
    float* sc = sm;
#pragma unroll
    for (int h = 0; h < 2; h++) {
        if ((wn >> 2) == h) {
            const int cb = nbase - h * 128;
#pragma unroll
            for (int mf = 0; mf < 4; mf++) {
                int r0 = mbase + mf * 16 + g;
#pragma unroll
                for (int nf = 0; nf < 4; nf++) {
                    int c0 = cb + nf * 8 + tig * 2;
                    sc[(r0)     * SCR_STR + c0]     = __expf(acc[mf][nf][0]);
                    sc[(r0)     * SCR_STR + c0 + 1] = __expf(acc[mf][nf][1]);
                    sc[(r0 + 8) * SCR_STR + c0]     = __expf(acc[mf][nf][2]);
                    sc[(r0 + 8) * SCR_STR + c0 + 1] = __expf(acc[mf][nf][3]);
                }
            }
        }
        __syncthreads();
#pragma unroll 4
        for (int it = 0; it < 8; it++) {
            int idx = it * NTHR + t;
            int r   = idx >> 5;            // row 0..127 (constant per warp)
            int c4  = idx & 31;
            int n   = n0 + h * 128 + c4 * 4;
            float4 v; float s;
            bool valid = (n < NDIM);
            if (valid) {
                v = *reinterpret_cast<const float4*>(sc + r * SCR_STR + c4 * 4);
                s = v.x + v.y + v.z + v.w;
                *reinterpret_cast<float4*>(out + (size_t)(m0 + r) * NDIM + n) = v;
            } else s = 0.f;
#pragma unroll
            for (int o = 16; o > 0; o >>= 1) s += __shfl_down_sync(0xffffffffu, s, o);
            if (lid == 0)
                g_part[(size_t)(m0 + r) * PW + pn * 2 + h] = s;
        }
        __syncthreads();
    }
}

// ---------------------------------------------------------------------------
__global__ void reduce_kernel(const float* __restrict__ loglib) {
    int row = blockIdx.x;
    float s = 0.f;
    for (int i = threadIdx.x; i < PW; i += 32) s += g_part[(size_t)row * PW + i];
#pragma unroll
    for (int o = 16; o > 0; o >>= 1) s += __shfl_down_sync(0xffffffffu, s, o);
    if (threadIdx.x == 0) g_scale[row] = expf(loglib[row]) / s;
}

__global__ void scale_kernel(float* __restrict__ out) {
    const int RF4 = NDIM / 4;
    long i = (long)blockIdx.x * blockDim.x + threadIdx.x;
    if (i >= (long)BDIM * RF4) return;
    int row = (int)(i / RF4);
    float s = g_scale[row];
    float4 v = reinterpret_cast<float4*>(out)[i];
    v.x *= s; v.y *= s; v.z *= s; v.w *= s;
    reinterpret_cast<float4*>(out)[i] = v;
}

// ---------------------------------------------------------------------------
extern "C" void kernel_launch(void* const* d_in, const int* in_sizes, int n_in,
                              void* d_out, int out_size) {
    const float* z      = (const float*)d_in[0];
    const float* loglib = (const float*)d_in[1];
    const float* cov    = (const float*)d_in[2];
    const float* mask   = (const float*)d_in[3];
    const float* amask  = (const float*)d_in[4];
    const float* Wm     = (const float*)d_in[5];
    const float* Wa     = (const float*)d_in[6];
    const float* Wc     = (const float*)d_in[7];
    float* out = (float*)d_out;

    cudaFuncSetAttribute(gemm_exp_kernel, cudaFuncAttributeMaxDynamicSharedMemorySize, SMEM_BYTES);

    {
        int total = BDIM * (KDIM / 8);
        build_A_kernel<<<(total + 255) / 256, 256>>>(z, cov);
    }
    {
        int total = KDIM * (NPAD / 8);
        build_W_kernel<<<(total + 255) / 256, 256>>>(Wm, mask, Wa, amask, Wc);
    }
    gemm_exp_kernel<<<GRID_M * GRID_N, NTHR, SMEM_BYTES>>>(out);
    reduce_kernel<<<BDIM, 32>>>(loglib);
    {
        long total = (long)BDIM * (NDIM / 4);
        scale_kernel<<<(unsigned)((total + 255) / 256), 256>>>(out);
    }
}

// round 8
// speedup vs baseline: 6.9401x; 1.0830x over previous
#include <cuda_runtime.h>
#include <cuda_fp16.h>
#include <cstdint>

#define BDIM   8192
#define KDIM   2336
#define NDIM   20000
#define NPAD   20224   // 79 * 256
#define ZW     2304
#define NPROW  2048
#define NAROW  256
#define NCROW  32

#define BM     128
#define BN     256
#define BK     32
#define NKT    73      // KDIM / BK
#define STAGES 6
#define GRID_M 64
#define GRID_N 79
#define GROUP  16
#define NTHR   512     // 16 warps: 2 (m) x 8 (n), 64x32 warp tiles

#define APITCH 272     // bytes per k-row of packed A tile (17*16, ldsm conflict-free)
#define BPITCH 528     // bytes per k-row of packed B tile (33*16)
#define A_TILE_B (32 * APITCH)   // 8704
#define B_TILE_B (32 * BPITCH)   // 16896
#define STAGE_B  (A_TILE_B + B_TILE_B)          // 25600
#define SMEM_BYTES (64 + STAGES * STAGE_B)      // 153664
#define SCR_STR 132
#define PW      158    // 79 n-blocks * 2 halves

// Tile-order packed operands (padding baked in -> ONE bulk copy per tile)
__device__ __align__(16) unsigned char g_Apack[(size_t)GRID_M * NKT * A_TILE_B];  // ~40.7 MB
__device__ __align__(16) unsigned char g_Wpack[(size_t)GRID_N * NKT * B_TILE_B];  // ~97.4 MB
__device__ float g_part[(size_t)BDIM * PW];
__device__ float g_scale[BDIM];

// ---------------------------------------------------------------------------
__device__ __forceinline__ uint32_t smem_u32(const void* p) {
    uint32_t a;
    asm("{ .reg .u64 t; cvta.to.shared.u64 t, %1; cvt.u32.u64 %0, t; }" : "=r"(a) : "l"(p));
    return a;
}
__device__ __forceinline__ void mbar_init(uint32_t m, uint32_t cnt) {
    asm volatile("mbarrier.init.shared.b64 [%0], %1;" :: "r"(m), "r"(cnt) : "memory");
}
__device__ __forceinline__ void mbar_expect_tx(uint32_t m, uint32_t bytes) {
    asm volatile("mbarrier.arrive.expect_tx.shared.b64 _, [%0], %1;" :: "r"(m), "r"(bytes) : "memory");
}
__device__ __forceinline__ void mbar_wait(uint32_t m, uint32_t ph) {
    uint32_t done;
    asm volatile("{\n\t.reg .pred p;\n\tmbarrier.try_wait.parity.acquire.cta.shared::cta.b64 p, [%1], %2;\n\tselp.b32 %0, 1, 0, p;\n\t}"
                 : "=r"(done) : "r"(m), "r"(ph) : "memory");
    while (!done) {
        asm volatile("{\n\t.reg .pred p;\n\tmbarrier.try_wait.parity.acquire.cta.shared::cta.b64 p, [%1], %2, 0x989680;\n\tselp.b32 %0, 1, 0, p;\n\t}"
                     : "=r"(done) : "r"(m), "r"(ph) : "memory");
    }
}
__device__ __forceinline__ void bulk_g2s(uint32_t dst, const void* src, uint32_t bytes, uint32_t mbar) {
    asm volatile("cp.async.bulk.shared::cluster.global.mbarrier::complete_tx::bytes [%0], [%1], %2, [%3];"
                 :: "r"(dst), "l"(src), "r"(bytes), "r"(mbar) : "memory");
}
__device__ __forceinline__ void ldsm_x4_t(uint32_t* r, uint32_t addr) {
    asm volatile("ldmatrix.sync.aligned.m8n8.x4.trans.shared.b16 {%0,%1,%2,%3}, [%4];"
                 : "=r"(r[0]), "=r"(r[1]), "=r"(r[2]), "=r"(r[3]) : "r"(addr));
}
__device__ __forceinline__ void mma_f16(float* d, const uint32_t* a, const uint32_t* b) {
    asm volatile("mma.sync.aligned.m16n8k16.row.col.f32.f16.f16.f32 "
                 "{%0,%1,%2,%3}, {%4,%5,%6,%7}, {%8,%9}, {%0,%1,%2,%3};"
                 : "+f"(d[0]), "+f"(d[1]), "+f"(d[2]), "+f"(d[3])
                 : "r"(a[0]), "r"(a[1]), "r"(a[2]), "r"(a[3]), "r"(b[0]), "r"(b[1]));
}
__device__ __forceinline__ uint32_t pack_h2(float x, float y) {
    __half2 h = __float22half2_rn(make_float2(x, y));
    return *reinterpret_cast<uint32_t*>(&h);
}

// ---------------------------------------------------------------------------
// Pack A tiles: [mblk][kt] -> 32 k-rows x 272B (128 m fp16 + 16B pad), via smem transpose
__global__ void build_Apack_kernel(const float* __restrict__ z, const float* __restrict__ cov) {
    __shared__ __align__(16) __half s[32][136];
    const int b = blockIdx.x;               // mblk*NKT + kt
    const int mblk = b / NKT, kt = b - mblk * NKT;
    const int m0 = mblk * BM, k0 = kt * BK;
    const int tid = threadIdx.x;
    for (int i = tid; i < BM * BK; i += 256) {
        int m = i >> 5, k = i & 31;
        int col = k0 + k;
        float v = (col < ZW) ? z[(size_t)(m0 + m) * ZW + col]
                             : cov[(size_t)(m0 + m) * NCROW + (col - ZW)];
        s[k][m] = __float2half(v);
    }
    __syncthreads();
    unsigned char* dst = g_Apack + (size_t)b * A_TILE_B;
    for (int i = tid; i < 544; i += 256) {        // 544 = 32 * 17 chunks of 16B
        int k = i / 17, c = i - k * 17;
        *reinterpret_cast<uint4*>(dst + k * APITCH + c * 16) =
            *reinterpret_cast<const uint4*>(&s[k][c * 8]);
    }
}

// Pack W tiles: [nblk][kt] -> 32 k-rows x 528B (256 n fp16 + 16B pad), mask fused
__global__ void build_Wpack_kernel(const float* __restrict__ Wm, const float* __restrict__ mask,
                                   const float* __restrict__ Wa, const float* __restrict__ am,
                                   const float* __restrict__ Wc) {
    const size_t total = (size_t)GRID_N * NKT * 32 * 33;     // 16B chunks
    size_t idx = (size_t)blockIdx.x * blockDim.x + threadIdx.x;
    if (idx >= total) return;
    int c    = (int)(idx % 33);
    size_t q = idx / 33;
    int k    = (int)(q % 32);
    size_t r = q / 32;
    int kt   = (int)(r % NKT);
    int nblk = (int)(r / NKT);
    unsigned char* dst = g_Wpack + ((size_t)nblk * NKT + kt) * B_TILE_B + k * BPITCH + c * 16;
    if (c == 32) {      // pad chunk
        *reinterpret_cast<uint4*>(dst) = make_uint4(0, 0, 0, 0);
        return;
    }
    int kk = kt * BK + k;
    int n  = nblk * BN + c * 8;
    float4 v0, v1;
    if (n + 7 >= NDIM) {
        float t[8];
#pragma unroll
        for (int j = 0; j < 8; j++) {
            int nn = n + j;
            float x = 0.f;
            if (nn < NDIM) {
                if (kk < NPROW)            x = Wm[(size_t)kk * NDIM + nn] * mask[(size_t)kk * NDIM + nn];
                else if (kk < NPROW+NAROW) x = Wa[(size_t)(kk-NPROW) * NDIM + nn] * am[(size_t)(kk-NPROW) * NDIM + nn];
                else                       x = Wc[(size_t)(kk-NPROW-NAROW) * NDIM + nn];
            }
            t[j] = x;
        }
        v0 = make_float4(t[0], t[1], t[2], t[3]);
        v1 = make_float4(t[4], t[5], t[6], t[7]);
    } else if (kk < NPROW) {
        float4 w0 = *reinterpret_cast<const float4*>(Wm + (size_t)kk * NDIM + n);
        float4 w1 = *reinterpret_cast<const float4*>(Wm + (size_t)kk * NDIM + n + 4);
        float4 m0 = *reinterpret_cast<const float4*>(mask + (size_t)kk * NDIM + n);
        float4 m1 = *reinterpret_cast<const float4*>(mask + (size_t)kk * NDIM + n + 4);
        v0 = make_float4(w0.x*m0.x, w0.y*m0.y, w0.z*m0.z, w0.w*m0.w);
        v1 = make_float4(w1.x*m1.x, w1.y*m1.y, w1.z*m1.z, w1.w*m1.w);
    } else if (kk < NPROW + NAROW) {
        int k2 = kk - NPROW;
        float4 w0 = *reinterpret_cast<const float4*>(Wa + (size_t)k2 * NDIM + n);
        float4 w1 = *reinterpret_cast<const float4*>(Wa + (size_t)k2 * NDIM + n + 4);
        float4 m0 = *reinterpret_cast<const float4*>(am + (size_t)k2 * NDIM + n);
        float4 m1 = *reinterpret_cast<const float4*>(am + (size_t)k2 * NDIM + n + 4);
        v0 = make_float4(w0.x*m0.x, w0.y*m0.y, w0.z*m0.z, w0.w*m0.w);
        v1 = make_float4(w1.x*m1.x, w1.y*m1.y, w1.z*m1.z, w1.w*m1.w);
    } else {
        int k2 = kk - NPROW - NAROW;
        v0 = *reinterpret_cast<const float4*>(Wc + (size_t)k2 * NDIM + n);
        v1 = *reinterpret_cast<const float4*>(Wc + (size_t)k2 * NDIM + n + 4);
    }
    uint4 o;
    o.x = pack_h2(v0.x, v0.y); o.y = pack_h2(v0.z, v0.w);
    o.z = pack_h2(v1.x, v1.y); o.w = pack_h2(v1.z, v1.w);
    *reinterpret_cast<uint4*>(dst) = o;
}

// ---------------------------------------------------------------------------
// fp16 mma.sync GEMM: bulk-TMA loads (2 per k-iter), mbarrier pipeline, 16 warps.
__global__ __launch_bounds__(NTHR, 1)
void gemm_exp_kernel(float* __restrict__ out) {
    extern __shared__ __align__(16) unsigned char smx[];
    float* sm = reinterpret_cast<float*>(smx);
    const uint32_t sb0 = smem_u32(smx);
    const int t   = threadIdx.x;
    const int wid = t >> 5;
    const int lid = t & 31;
    const int g   = lid >> 2;
    const int tig = lid & 3;

    const int per = GROUP * GRID_N;
    int bid = blockIdx.x;
    int grp = bid / per;
    int loc = bid - grp * per;
    int pm  = grp * GROUP + (loc & (GROUP - 1));
    int pn  = loc >> 4;
    const int m0 = pm * BM;
    const int n0 = pn * BN;

    const int wm = wid >> 3;      // 0..1
    const int wn = wid & 7;       // 0..7
    const int mbase = wm * 64;
    const int nbase = wn * 32;

    float acc[4][4][4];
#pragma unroll
    for (int i = 0; i < 4; i++)
#pragma unroll
        for (int j = 0; j < 4; j++)
#pragma unroll
            for (int q = 0; q < 4; q++) acc[i][j][q] = 0.f;

    if (t == 0) {
#pragma unroll
        for (int s = 0; s < STAGES; s++) mbar_init(sb0 + s * 8, 1);
    }
    __syncthreads();

    const unsigned char* srcA = g_Apack + (size_t)pm * NKT * A_TILE_B;
    const unsigned char* srcB = g_Wpack + (size_t)pn * NKT * B_TILE_B;

    auto issue_stage = [&](int slot, int ks) {
        const uint32_t mb  = sb0 + slot * 8;
        const uint32_t stg = sb0 + 64 + slot * STAGE_B;
        mbar_expect_tx(mb, STAGE_B);
        bulk_g2s(stg,            srcA + (size_t)ks * A_TILE_B, A_TILE_B, mb);
        bulk_g2s(stg + A_TILE_B, srcB + (size_t)ks * B_TILE_B, B_TILE_B, mb);
    };

    if (t == 0) {
#pragma unroll
        for (int s = 0; s < STAGES; s++) issue_stage(s, s);
    }

    // ldmatrix lane addressing (both operands .trans from k-major tiles)
    const int laneRow = (lid & 7) + ((lid >> 3) & 1) * 8;   // 0..15
    const int laneHi  = (lid >> 4);                          // 0 or 1
    const uint32_t offA = (uint32_t)laneRow * APITCH + (uint32_t)(mbase + laneHi * 8) * 2;
    const uint32_t offB = (uint32_t)laneRow * BPITCH + (uint32_t)(nbase + laneHi * 8) * 2;

    int ph = 0;
    for (int kt = 0; kt < NKT; kt++) {
        const int slot = kt % STAGES;
        mbar_wait(sb0 + slot * 8, ph);
        if (slot == STAGES - 1) ph ^= 1;

        const uint32_t stg = sb0 + 64 + slot * STAGE_B;
        const uint32_t pA = stg + offA;
        const uint32_t pB = stg + A_TILE_B + offB;

#pragma unroll
        for (int kk = 0; kk < BK; kk += 16) {
            uint32_t af[4][4], bf[4][2];
#pragma unroll
            for (int mf = 0; mf < 4; mf++) {
                uint32_t r[4];
                ldsm_x4_t(r, pA + kk * APITCH + mf * 32);
                af[mf][0] = r[0]; af[mf][1] = r[2]; af[mf][2] = r[1]; af[mf][3] = r[3];
            }
#pragma unroll
            for (int nf2 = 0; nf2 < 2; nf2++) {
                uint32_t r[4];
                ldsm_x4_t(r, pB + kk * BPITCH + nf2 * 32);
                bf[nf2 * 2][0]     = r[0]; bf[nf2 * 2][1]     = r[1];
                bf[nf2 * 2 + 1][0] = r[2]; bf[nf2 * 2 + 1][1] = r[3];
            }
#pragma unroll
            for (int mf = 0; mf < 4; mf++)
#pragma unroll
                for (int nf = 0; nf < 4; nf++)
                    mma_f16(acc[mf][nf], af[mf], bf[nf]);
        }
        __syncthreads();
        if (t == 0 && kt + STAGES < NKT) issue_stage(slot, kt + STAGES);
    }

    // ---- epilogue in two 128-col halves: exp -> scratch -> store + partials ----
    float* sc = sm;
#pragma unroll
    for (int h = 0; h < 2; h++) {
        if ((wn >> 2) == h) {
            const int cb = nbase - h * 128;
#pragma unroll
            for (int mf = 0; mf < 4; mf++) {
                int r0 = mbase + mf * 16 + g;
#pragma unroll
                for (int nf = 0; nf < 4; nf++) {
                    int c0 = cb + nf * 8 + tig * 2;
                    sc[(r0)     * SCR_STR + c0]     = __expf(acc[mf][nf][0]);
                    sc[(r0)     * SCR_STR + c0 + 1] = __expf(acc[mf][nf][1]);
                    sc[(r0 + 8) * SCR_STR + c0]     = __expf(acc[mf][nf][2]);
                    sc[(r0 + 8) * SCR_STR + c0 + 1] = __expf(acc[mf][nf][3]);
                }
            }
        }
        __syncthreads();
#pragma unroll 4
        for (int it = 0; it < 8; it++) {
            int idx = it * NTHR + t;
            int r   = idx >> 5;
            int c4  = idx & 31;
            int n   = n0 + h * 128 + c4 * 4;
            float4 v; float s;
            bool valid = (n < NDIM);
            if (valid) {
                v = *reinterpret_cast<const float4*>(sc + r * SCR_STR + c4 * 4);
                s = v.x + v.y + v.z + v.w;
                *reinterpret_cast<float4*>(out + (size_t)(m0 + r) * NDIM + n) = v;
            } else s = 0.f;
#pragma unroll
            for (int o = 16; o > 0; o >>= 1) s += __shfl_down_sync(0xffffffffu, s, o);
            if (lid == 0)
                g_part[(size_t)(m0 + r) * PW + pn * 2 + h] = s;
        }
        __syncthreads();
    }
}

// ---------------------------------------------------------------------------
__global__ void reduce_kernel(const float* __restrict__ loglib) {
    int row = blockIdx.x;
    float s = 0.f;
    for (int i = threadIdx.x; i < PW; i += 32) s += g_part[(size_t)row * PW + i];
#pragma unroll
    for (int o = 16; o > 0; o >>= 1) s += __shfl_down_sync(0xffffffffu, s, o);
    if (threadIdx.x == 0) g_scale[row] = expf(loglib[row]) / s;
}

__global__ void scale_kernel(float* __restrict__ out) {
    const int RF4 = NDIM / 4;
    long i = (long)blockIdx.x * blockDim.x + threadIdx.x;
    if (i >= (long)BDIM * RF4) return;
    int row = (int)(i / RF4);
    float s = g_scale[row];
    float4 v = reinterpret_cast<float4*>(out)[i];
    v.x *= s; v.y *= s; v.z *= s; v.w *= s;
    reinterpret_cast<float4*>(out)[i] = v;
}

// ---------------------------------------------------------------------------
extern "C" void kernel_launch(void* const* d_in, const int* in_sizes, int n_in,
                              void* d_out, int out_size) {
    const float* z      = (const float*)d_in[0];
    const float* loglib = (const float*)d_in[1];
    const float* cov    = (const float*)d_in[2];
    const float* mask   = (const float*)d_in[3];
    const float* amask  = (const float*)d_in[4];
    const float* Wm     = (const float*)d_in[5];
    const float* Wa     = (const float*)d_in[6];
    const float* Wc     = (const float*)d_in[7];
    float* out = (float*)d_out;

    cudaFuncSetAttribute(gemm_exp_kernel, cudaFuncAttributeMaxDynamicSharedMemorySize, SMEM_BYTES);

    build_Apack_kernel<<<GRID_M * NKT, 256>>>(z, cov);
    {
        size_t total = (size_t)GRID_N * NKT * 32 * 33;
        build_Wpack_kernel<<<(unsigned)((total + 255) / 256), 256>>>(Wm, mask, Wa, amask, Wc);
    }
    gemm_exp_kernel<<<GRID_M * GRID_N, NTHR, SMEM_BYTES>>>(out);
    reduce_kernel<<<BDIM, 32>>>(loglib);
    {
        long total = (long)BDIM * (NDIM / 4);
        scale_kernel<<<(unsigned)((total + 255) / 256), 256>>>(out);
    }
}

// round 9
// speedup vs baseline: 7.4537x; 1.0740x over previous
#include <cuda_runtime.h>
#include <cuda_fp16.h>
#include <cstdint>

#define BDIM   8192
#define KDIM   2336
#define KPAD   2368    // 37 * 64
#define NDIM   20000
#define ZW     2304
#define NPROW  2048
#define NAROW  256
#define NCROW  32

#define BM     128
#define BN     256
#define BK     64
#define NKT    37      // KPAD / BK
#define STAGES 4
#define GRID_M 64
#define GRID_N 79
#define GROUP  16
#define NTHR   512     // 16 warps: 2 (m) x 8 (n), 64x32 warp tiles

#define APITCH 272     // bytes per k-row of packed A tile (17*16)
#define BPITCH 528     // bytes per k-row of packed B tile (33*16)
#define A_TILE_B (BK * APITCH)   // 17408
#define B_TILE_B (BK * BPITCH)   // 33792
#define STAGE_B  (A_TILE_B + B_TILE_B)          // 51200
#define SMEM_BYTES (64 + STAGES * STAGE_B)      // 204864
#define SCR_STR 132
#define PW      158    // 79 n-blocks * 2 halves

__device__ __align__(16) unsigned char g_Apack[(size_t)GRID_M * NKT * A_TILE_B];  // ~41 MB
__device__ __align__(16) unsigned char g_Wpack[(size_t)GRID_N * NKT * B_TILE_B];  // ~99 MB
__device__ float g_part[(size_t)BDIM * PW];
__device__ float g_scale[BDIM];

// ---------------------------------------------------------------------------
__device__ __forceinline__ uint32_t smem_u32(const void* p) {
    uint32_t a;
    asm("{ .reg .u64 t; cvta.to.shared.u64 t, %1; cvt.u32.u64 %0, t; }" : "=r"(a) : "l"(p));
    return a;
}
__device__ __forceinline__ void mbar_init(uint32_t m, uint32_t cnt) {
    asm volatile("mbarrier.init.shared.b64 [%0], %1;" :: "r"(m), "r"(cnt) : "memory");
}
__device__ __forceinline__ void mbar_arrive(uint32_t m) {
    asm volatile("mbarrier.arrive.release.cta.shared::cta.b64 _, [%0];" :: "r"(m) : "memory");
}
__device__ __forceinline__ void mbar_expect_tx(uint32_t m, uint32_t bytes) {
    asm volatile("mbarrier.arrive.expect_tx.shared.b64 _, [%0], %1;" :: "r"(m), "r"(bytes) : "memory");
}
__device__ __forceinline__ void mbar_wait(uint32_t m, uint32_t ph) {
    uint32_t done;
    asm volatile("{\n\t.reg .pred p;\n\tmbarrier.try_wait.parity.acquire.cta.shared::cta.b64 p, [%1], %2;\n\tselp.b32 %0, 1, 0, p;\n\t}"
                 : "=r"(done) : "r"(m), "r"(ph) : "memory");
    while (!done) {
        asm volatile("{\n\t.reg .pred p;\n\tmbarrier.try_wait.parity.acquire.cta.shared::cta.b64 p, [%1], %2, 0x989680;\n\tselp.b32 %0, 1, 0, p;\n\t}"
                     : "=r"(done) : "r"(m), "r"(ph) : "memory");
    }
}
__device__ __forceinline__ void bulk_g2s(uint32_t dst, const void* src, uint32_t bytes, uint32_t mbar) {
    asm volatile("cp.async.bulk.shared::cluster.global.mbarrier::complete_tx::bytes [%0], [%1], %2, [%3];"
                 :: "r"(dst), "l"(src), "r"(bytes), "r"(mbar) : "memory");
}
__device__ __forceinline__ void ldsm_x4_t(uint32_t* r, uint32_t addr) {
    asm volatile("ldmatrix.sync.aligned.m8n8.x4.trans.shared.b16 {%0,%1,%2,%3}, [%4];"
                 : "=r"(r[0]), "=r"(r[1]), "=r"(r[2]), "=r"(r[3]) : "r"(addr));
}
__device__ __forceinline__ void mma_f16(float* d, const uint32_t* a, const uint32_t* b) {
    asm volatile("mma.sync.aligned.m16n8k16.row.col.f32.f16.f16.f32 "
                 "{%0,%1,%2,%3}, {%4,%5,%6,%7}, {%8,%9}, {%0,%1,%2,%3};"
                 : "+f"(d[0]), "+f"(d[1]), "+f"(d[2]), "+f"(d[3])
                 : "r"(a[0]), "r"(a[1]), "r"(a[2]), "r"(a[3]), "r"(b[0]), "r"(b[1]));
}
__device__ __forceinline__ uint32_t pack_h2(float x, float y) {
    __half2 h = __float22half2_rn(make_float2(x, y));
    return *reinterpret_cast<uint32_t*>(&h);
}

// ---------------------------------------------------------------------------
// Pack A tiles: [mblk][kt] -> 64 k-rows x 272B (128 m fp16 + pad), smem transpose
__global__ void build_Apack_kernel(const float* __restrict__ z, const float* __restrict__ cov) {
    __shared__ __align__(16) __half s[BK][136];
    const int b = blockIdx.x;               // mblk*NKT + kt
    const int mblk = b / NKT, kt = b - mblk * NKT;
    const int m0 = mblk * BM, k0 = kt * BK;
    const int tid = threadIdx.x;
    for (int i = tid; i < BM * BK; i += 256) {
        int m = i >> 6, k = i & 63;
        int col = k0 + k;
        float v = 0.f;
        if (col < ZW)       v = z[(size_t)(m0 + m) * ZW + col];
        else if (col < KDIM) v = cov[(size_t)(m0 + m) * NCROW + (col - ZW)];
        s[k][m] = __float2half(v);
    }
    __syncthreads();
    unsigned char* dst = g_Apack + (size_t)b * A_TILE_B;
    for (int i = tid; i < BK * 17; i += 256) {
        int k = i / 17, c = i - k * 17;
        *reinterpret_cast<uint4*>(dst + k * APITCH + c * 16) =
            *reinterpret_cast<const uint4*>(&s[k][c * 8]);
    }
}

// Pack W tiles: [nblk][kt] -> 64 k-rows x 528B (256 n fp16 + pad), mask fused
__global__ void build_Wpack_kernel(const float* __restrict__ Wm, const float* __restrict__ mask,
                                   const float* __restrict__ Wa, const float* __restrict__ am,
                                   const float* __restrict__ Wc) {
    const size_t total = (size_t)GRID_N * NKT * BK * 33;     // 16B chunks
    size_t idx = (size_t)blockIdx.x * blockDim.x + threadIdx.x;
    if (idx >= total) return;
    int c    = (int)(idx % 33);
    size_t q = idx / 33;
    int k    = (int)(q % BK);
    size_t r = q / BK;
    int kt   = (int)(r % NKT);
    int nblk = (int)(r / NKT);
    unsigned char* dst = g_Wpack + ((size_t)nblk * NKT + kt) * B_TILE_B + k * BPITCH + c * 16;
    int kk = kt * BK + k;
    if (c == 32 || kk >= KDIM) {
        *reinterpret_cast<uint4*>(dst) = make_uint4(0, 0, 0, 0);
        return;
    }
    int n = nblk * BN + c * 8;
    float4 v0, v1;
    if (n + 7 >= NDIM) {
        float t[8];
#pragma unroll
        for (int j = 0; j < 8; j++) {
            int nn = n + j;
            float x = 0.f;
            if (nn < NDIM) {
                if (kk < NPROW)            x = Wm[(size_t)kk * NDIM + nn] * mask[(size_t)kk * NDIM + nn];
                else if (kk < NPROW+NAROW) x = Wa[(size_t)(kk-NPROW) * NDIM + nn] * am[(size_t)(kk-NPROW) * NDIM + nn];
                else                       x = Wc[(size_t)(kk-NPROW-NAROW) * NDIM + nn];
            }
            t[j] = x;
        }
        v0 = make_float4(t[0], t[1], t[2], t[3]);
        v1 = make_float4(t[4], t[5], t[6], t[7]);
    } else if (kk < NPROW) {
        float4 w0 = *reinterpret_cast<const float4*>(Wm + (size_t)kk * NDIM + n);
        float4 w1 = *reinterpret_cast<const float4*>(Wm + (size_t)kk * NDIM + n + 4);
        float4 m0 = *reinterpret_cast<const float4*>(mask + (size_t)kk * NDIM + n);
        float4 m1 = *reinterpret_cast<const float4*>(mask + (size_t)kk * NDIM + n + 4);
        v0 = make_float4(w0.x*m0.x, w0.y*m0.y, w0.z*m0.z, w0.w*m0.w);
        v1 = make_float4(w1.x*m1.x, w1.y*m1.y, w1.z*m1.z, w1.w*m1.w);
    } else if (kk < NPROW + NAROW) {
        int k2 = kk - NPROW;
        float4 w0 = *reinterpret_cast<const float4*>(Wa + (size_t)k2 * NDIM + n);
        float4 w1 = *reinterpret_cast<const float4*>(Wa + (size_t)k2 * NDIM + n + 4);
        float4 m0 = *reinterpret_cast<const float4*>(am + (size_t)k2 * NDIM + n);
        float4 m1 = *reinterpret_cast<const float4*>(am + (size_t)k2 * NDIM + n + 4);
        v0 = make_float4(w0.x*m0.x, w0.y*m0.y, w0.z*m0.z, w0.w*m0.w);
        v1 = make_float4(w1.x*m1.x, w1.y*m1.y, w1.z*m1.z, w1.w*m1.w);
    } else {
        int k2 = kk - NPROW - NAROW;
        v0 = *reinterpret_cast<const float4*>(Wc + (size_t)k2 * NDIM + n);
        v1 = *reinterpret_cast<const float4*>(Wc + (size_t)k2 * NDIM + n + 4);
    }
    uint4 o;
    o.x = pack_h2(v0.x, v0.y); o.y = pack_h2(v0.z, v0.w);
    o.z = pack_h2(v1.x, v1.y); o.w = pack_h2(v1.z, v1.w);
    *reinterpret_cast<uint4*>(dst) = o;
}

// ---------------------------------------------------------------------------
// fp16 mma.sync GEMM: bulk-TMA, BK=64, 4-stage mbarrier ring, NO mainloop bar.
__global__ __launch_bounds__(NTHR, 1)
void gemm_exp_kernel(float* __restrict__ out) {
    extern __shared__ __align__(16) unsigned char smx[];
    float* sm = reinterpret_cast<float*>(smx);
    const uint32_t sb0 = smem_u32(smx);          // [0..31] full, [32..63] free
    const int t   = threadIdx.x;
    const int wid = t >> 5;
    const int lid = t & 31;
    const int g   = lid >> 2;
    const int tig = lid & 3;

    const int per = GROUP * GRID_N;
    int bid = blockIdx.x;
    int grp = bid / per;
    int loc = bid - grp * per;
    int pm  = grp * GROUP + (loc & (GROUP - 1));
    int pn  = loc >> 4;
    const int m0 = pm * BM;
    const int n0 = pn * BN;

    const int wm = wid >> 3;
    const int wn = wid & 7;
    const int mbase = wm * 64;
    const int nbase = wn * 32;

    float acc[4][4][4];
#pragma unroll
    for (int i = 0; i < 4; i++)
#pragma unroll
        for (int j = 0; j < 4; j++)
#pragma unroll
            for (int q = 0; q < 4; q++) acc[i][j][q] = 0.f;

    if (t == 0) {
#pragma unroll
        for (int s = 0; s < STAGES; s++) {
            mbar_init(sb0 + s * 8, 1);           // full: tx-based
            mbar_init(sb0 + 32 + s * 8, 16);     // free: 16 warp arrivals
        }
    }
    __syncthreads();

    const unsigned char* srcA = g_Apack + (size_t)pm * NKT * A_TILE_B;
    const unsigned char* srcB = g_Wpack + (size_t)pn * NKT * B_TILE_B;

    auto issue_stage = [&](int slot, int ks) {
        const uint32_t mb  = sb0 + slot * 8;
        const uint32_t stg = sb0 + 64 + slot * STAGE_B;
        mbar_expect_tx(mb, STAGE_B);
        bulk_g2s(stg,            srcA + (size_t)ks * A_TILE_B, A_TILE_B, mb);
        bulk_g2s(stg + A_TILE_B, srcB + (size_t)ks * B_TILE_B, B_TILE_B, mb);
    };

    if (t == 0) {
#pragma unroll
        for (int s = 0; s < STAGES; s++) issue_stage(s, s);
    }

    const int laneRow = (lid & 7) + ((lid >> 3) & 1) * 8;   // 0..15
    const int laneHi  = (lid >> 4);                          // 0 or 1
    const uint32_t offA = (uint32_t)laneRow * APITCH + (uint32_t)(mbase + laneHi * 8) * 2;
    const uint32_t offB = (uint32_t)laneRow * BPITCH + (uint32_t)(nbase + laneHi * 8) * 2;

    int ph = 0, fph = 0;
    for (int kt = 0; kt < NKT; kt++) {
        const int slot = kt & (STAGES - 1);
        mbar_wait(sb0 + slot * 8, ph);

        const uint32_t stg = sb0 + 64 + slot * STAGE_B;
        const uint32_t pA = stg + offA;
        const uint32_t pB = stg + A_TILE_B + offB;

#pragma unroll
        for (int kk = 0; kk < BK; kk += 16) {
            uint32_t af[4][4], bf[4][2];
#pragma unroll
            for (int mf = 0; mf < 4; mf++) {
                uint32_t r[4];
                ldsm_x4_t(r, pA + kk * APITCH + mf * 32);
                af[mf][0] = r[0]; af[mf][1] = r[2]; af[mf][2] = r[1]; af[mf][3] = r[3];
            }
#pragma unroll
            for (int nf2 = 0; nf2 < 2; nf2++) {
                uint32_t r[4];
                ldsm_x4_t(r, pB + kk * BPITCH + nf2 * 32);
                bf[nf2 * 2][0]     = r[0]; bf[nf2 * 2][1]     = r[1];
                bf[nf2 * 2 + 1][0] = r[2]; bf[nf2 * 2 + 1][1] = r[3];
            }
#pragma unroll
            for (int mf = 0; mf < 4; mf++)
#pragma unroll
                for (int nf = 0; nf < 4; nf++)
                    mma_f16(acc[mf][nf], af[mf], bf[nf]);
        }

        if (lid == 0) mbar_arrive(sb0 + 32 + slot * 8);     // warp done with stage
        if (t == 0) {                                        // producer (warp0 lane0)
            int ks = kt + STAGES;
            if (ks < NKT) {
                mbar_wait(sb0 + 32 + slot * 8, fph);         // all 16 warps done
                issue_stage(slot, ks);
            }
        }
        if (slot == STAGES - 1) { ph ^= 1; fph ^= 1; }
    }

    __syncthreads();

    // ---- epilogue in two 128-col halves: exp -> scratch -> store + partials ----
    float* sc = sm;
#pragma unroll
    for (int h = 0; h < 2; h++) {
        if ((wn >> 2) == h) {
            const int cb = nbase - h * 128;
#pragma unroll
            for (int mf = 0; mf < 4; mf++) {
                int r0 = mbase + mf * 16 + g;
#pragma unroll
                for (int nf = 0; nf < 4; nf++) {
                    int c0 = cb + nf * 8 + tig * 2;
                    sc[(r0)     * SCR_STR + c0]     = __expf(acc[mf][nf][0]);
                    sc[(r0)     * SCR_STR + c0 + 1] = __expf(acc[mf][nf][1]);
                    sc[(r0 + 8) * SCR_STR + c0]     = __expf(acc[mf][nf][2]);
                    sc[(r0 + 8) * SCR_STR + c0 + 1] = __expf(acc[mf][nf][3]);
                }
            }
        }
        __syncthreads();
#pragma unroll 4
        for (int it = 0; it < 8; it++) {
            int idx = it * NTHR + t;
            int r   = idx >> 5;
            int c4  = idx & 31;
            int n   = n0 + h * 128 + c4 * 4;
            float4 v; float s;
            bool valid = (n < NDIM);
            if (valid) {
                v = *reinterpret_cast<const float4*>(sc + r * SCR_STR + c4 * 4);
                s = v.x + v.y + v.z + v.w;
                *reinterpret_cast<float4*>(out + (size_t)(m0 + r) * NDIM + n) = v;
            } else s = 0.f;
#pragma unroll
            for (int o = 16; o > 0; o >>= 1) s += __shfl_down_sync(0xffffffffu, s, o);
            if (lid == 0)
                g_part[(size_t)(m0 + r) * PW + pn * 2 + h] = s;
        }
        __syncthreads();
    }
}

// ---------------------------------------------------------------------------
__global__ void reduce_kernel(const float* __restrict__ loglib) {
    int row = blockIdx.x;
    float s = 0.f;
    for (int i = threadIdx.x; i < PW; i += 32) s += g_part[(size_t)row * PW + i];
#pragma unroll
    for (int o = 16; o > 0; o >>= 1) s += __shfl_down_sync(0xffffffffu, s, o);
    if (threadIdx.x == 0) g_scale[row] = expf(loglib[row]) / s;
}

__global__ void scale_kernel(float* __restrict__ out) {
    const int RF4 = NDIM / 4;
    long i = (long)blockIdx.x * blockDim.x + threadIdx.x;
    if (i >= (long)BDIM * RF4) return;
    int row = (int)(i / RF4);
    float s = g_scale[row];
    float4 v = reinterpret_cast<float4*>(out)[i];
    v.x *= s; v.y *= s; v.z *= s; v.w *= s;
    reinterpret_cast<float4*>(out)[i] = v;
}

// ---------------------------------------------------------------------------
extern "C" void kernel_launch(void* const* d_in, const int* in_sizes, int n_in,
                              void* d_out, int out_size) {
    const float* z      = (const float*)d_in[0];
    const float* loglib = (const float*)d_in[1];
    const float* cov    = (const float*)d_in[2];
    const float* mask   = (const float*)d_in[3];
    const float* amask  = (const float*)d_in[4];
    const float* Wm     = (const float*)d_in[5];
    const float* Wa     = (const float*)d_in[6];
    const float* Wc     = (const float*)d_in[7];
    float* out = (float*)d_out;

    cudaFuncSetAttribute(gemm_exp_kernel, cudaFuncAttributeMaxDynamicSharedMemorySize, SMEM_BYTES);

    build_Apack_kernel<<<GRID_M * NKT, 256>>>(z, cov);
    {
        size_t total = (size_t)GRID_N * NKT * BK * 33;
        build_Wpack_kernel<<<(unsigned)((total + 255) / 256), 256>>>(Wm, mask, Wa, amask, Wc);
    }
    gemm_exp_kernel<<<GRID_M * GRID_N, NTHR, SMEM_BYTES>>>(out);
    reduce_kernel<<<BDIM, 32>>>(loglib);
    {
        long total = (long)BDIM * (NDIM / 4);
        scale_kernel<<<(unsigned)((total + 255) / 256), 256>>>(out);
    }
}

// round 10
// speedup vs baseline: 7.7679x; 1.0421x over previous
#include <cuda_runtime.h>
#include <cuda_fp16.h>
#include <cstdint>

#define BDIM   8192
#define KDIM   2336
#define KPAD   2368    // 37 * 64
#define NDIM   20000
#define ZW     2304
#define NPROW  2048
#define NAROW  256
#define NCROW  32

#define BM     128
#define BN     256
#define BK     64
#define NKT    37      // KPAD / BK
#define STAGES 4
#define GRID_M 64
#define GRID_N 79
#define GROUP  16
#define NTHR   512     // 16 warps: 2 (m) x 8 (n), 64x32 warp tiles

#define APITCH 272     // bytes per k-row of packed A tile (17*16)
#define BPITCH 528     // bytes per k-row of packed B tile (33*16)
#define A_TILE_B (BK * APITCH)   // 17408
#define B_TILE_B (BK * BPITCH)   // 33792
#define STAGE_B  (A_TILE_B + B_TILE_B)          // 51200
#define SMEM_BYTES (64 + STAGES * STAGE_B)      // 204864
#define PW      632    // 79 n-blocks * 8 n-warps

__device__ __align__(16) unsigned char g_Apack[(size_t)GRID_M * NKT * A_TILE_B];  // ~41 MB
__device__ __align__(16) unsigned char g_Wpack[(size_t)GRID_N * NKT * B_TILE_B];  // ~99 MB
__device__ float g_part[(size_t)BDIM * PW];    // ~20.7 MB
__device__ float g_scale[BDIM];

// ---------------------------------------------------------------------------
__device__ __forceinline__ uint32_t smem_u32(const void* p) {
    uint32_t a;
    asm("{ .reg .u64 t; cvta.to.shared.u64 t, %1; cvt.u32.u64 %0, t; }" : "=r"(a) : "l"(p));
    return a;
}
__device__ __forceinline__ void mbar_init(uint32_t m, uint32_t cnt) {
    asm volatile("mbarrier.init.shared.b64 [%0], %1;" :: "r"(m), "r"(cnt) : "memory");
}
__device__ __forceinline__ void mbar_arrive(uint32_t m) {
    asm volatile("mbarrier.arrive.release.cta.shared::cta.b64 _, [%0];" :: "r"(m) : "memory");
}
__device__ __forceinline__ void mbar_expect_tx(uint32_t m, uint32_t bytes) {
    asm volatile("mbarrier.arrive.expect_tx.shared.b64 _, [%0], %1;" :: "r"(m), "r"(bytes) : "memory");
}
__device__ __forceinline__ void mbar_wait(uint32_t m, uint32_t ph) {
    uint32_t done;
    asm volatile("{\n\t.reg .pred p;\n\tmbarrier.try_wait.parity.acquire.cta.shared::cta.b64 p, [%1], %2;\n\tselp.b32 %0, 1, 0, p;\n\t}"
                 : "=r"(done) : "r"(m), "r"(ph) : "memory");
    while (!done) {
        asm volatile("{\n\t.reg .pred p;\n\tmbarrier.try_wait.parity.acquire.cta.shared::cta.b64 p, [%1], %2, 0x989680;\n\tselp.b32 %0, 1, 0, p;\n\t}"
                     : "=r"(done) : "r"(m), "r"(ph) : "memory");
    }
}
__device__ __forceinline__ void bulk_g2s(uint32_t dst, const void* src, uint32_t bytes, uint32_t mbar) {
    asm volatile("cp.async.bulk.shared::cluster.global.mbarrier::complete_tx::bytes [%0], [%1], %2, [%3];"
                 :: "r"(dst), "l"(src), "r"(bytes), "r"(mbar) : "memory");
}
__device__ __forceinline__ void ldsm_x4_t(uint32_t* r, uint32_t addr) {
    asm volatile("ldmatrix.sync.aligned.m8n8.x4.trans.shared.b16 {%0,%1,%2,%3}, [%4];"
                 : "=r"(r[0]), "=r"(r[1]), "=r"(r[2]), "=r"(r[3]) : "r"(addr));
}
__device__ __forceinline__ void mma_f16(float* d, const uint32_t* a, const uint32_t* b) {
    asm volatile("mma.sync.aligned.m16n8k16.row.col.f32.f16.f16.f32 "
                 "{%0,%1,%2,%3}, {%4,%5,%6,%7}, {%8,%9}, {%0,%1,%2,%3};"
                 : "+f"(d[0]), "+f"(d[1]), "+f"(d[2]), "+f"(d[3])
                 : "r"(a[0]), "r"(a[1]), "r"(a[2]), "r"(a[3]), "r"(b[0]), "r"(b[1]));
}
__device__ __forceinline__ uint32_t pack_h2(float x, float y) {
    __half2 h = __float22half2_rn(make_float2(x, y));
    return *reinterpret_cast<uint32_t*>(&h);
}

// ---------------------------------------------------------------------------
// Pack A tiles: [mblk][kt] -> 64 k-rows x 272B (128 m fp16 + pad), smem transpose
__global__ void build_Apack_kernel(const float* __restrict__ z, const float* __restrict__ cov) {
    __shared__ __align__(16) __half s[BK][136];
    const int b = blockIdx.x;               // mblk*NKT + kt
    const int mblk = b / NKT, kt = b - mblk * NKT;
    const int m0 = mblk * BM, k0 = kt * BK;
    const int tid = threadIdx.x;
    for (int i = tid; i < BM * BK; i += 256) {
        int m = i >> 6, k = i & 63;
        int col = k0 + k;
        float v = 0.f;
        if (col < ZW)       v = z[(size_t)(m0 + m) * ZW + col];
        else if (col < KDIM) v = cov[(size_t)(m0 + m) * NCROW + (col - ZW)];
        s[k][m] = __float2half(v);
    }
    __syncthreads();
    unsigned char* dst = g_Apack + (size_t)b * A_TILE_B;
    for (int i = tid; i < BK * 17; i += 256) {
        int k = i / 17, c = i - k * 17;
        *reinterpret_cast<uint4*>(dst + k * APITCH + c * 16) =
            *reinterpret_cast<const uint4*>(&s[k][c * 8]);
    }
}

// Pack W tiles: [nblk][kt] -> 64 k-rows x 528B (256 n fp16 + pad), mask fused
__global__ void build_Wpack_kernel(const float* __restrict__ Wm, const float* __restrict__ mask,
                                   const float* __restrict__ Wa, const float* __restrict__ am,
                                   const float* __restrict__ Wc) {
    const size_t total = (size_t)GRID_N * NKT * BK * 33;     // 16B chunks
    size_t idx = (size_t)blockIdx.x * blockDim.x + threadIdx.x;
    if (idx >= total) return;
    int c    = (int)(idx % 33);
    size_t q = idx / 33;
    int k    = (int)(q % BK);
    size_t r = q / BK;
    int kt   = (int)(r % NKT);
    int nblk = (int)(r / NKT);
    unsigned char* dst = g_Wpack + ((size_t)nblk * NKT + kt) * B_TILE_B + k * BPITCH + c * 16;
    int kk = kt * BK + k;
    if (c == 32 || kk >= KDIM) {
        *reinterpret_cast<uint4*>(dst) = make_uint4(0, 0, 0, 0);
        return;
    }
    int n = nblk * BN + c * 8;
    float4 v0, v1;
    if (n + 7 >= NDIM) {
        float t[8];
#pragma unroll
        for (int j = 0; j < 8; j++) {
            int nn = n + j;
            float x = 0.f;
            if (nn < NDIM) {
                if (kk < NPROW)            x = Wm[(size_t)kk * NDIM + nn] * mask[(size_t)kk * NDIM + nn];
                else if (kk < NPROW+NAROW) x = Wa[(size_t)(kk-NPROW) * NDIM + nn] * am[(size_t)(kk-NPROW) * NDIM + nn];
                else                       x = Wc[(size_t)(kk-NPROW-NAROW) * NDIM + nn];
            }
            t[j] = x;
        }
        v0 = make_float4(t[0], t[1], t[2], t[3]);
        v1 = make_float4(t[4], t[5], t[6], t[7]);
    } else if (kk < NPROW) {
        float4 w0 = *reinterpret_cast<const float4*>(Wm + (size_t)kk * NDIM + n);
        float4 w1 = *reinterpret_cast<const float4*>(Wm + (size_t)kk * NDIM + n + 4);
        float4 m0 = *reinterpret_cast<const float4*>(mask + (size_t)kk * NDIM + n);
        float4 m1 = *reinterpret_cast<const float4*>(mask + (size_t)kk * NDIM + n + 4);
        v0 = make_float4(w0.x*m0.x, w0.y*m0.y, w0.z*m0.z, w0.w*m0.w);
        v1 = make_float4(w1.x*m1.x, w1.y*m1.y, w1.z*m1.z, w1.w*m1.w);
    } else if (kk < NPROW + NAROW) {
        int k2 = kk - NPROW;
        float4 w0 = *reinterpret_cast<const float4*>(Wa + (size_t)k2 * NDIM + n);
        float4 w1 = *reinterpret_cast<const float4*>(Wa + (size_t)k2 * NDIM + n + 4);
        float4 m0 = *reinterpret_cast<const float4*>(am + (size_t)k2 * NDIM + n);
        float4 m1 = *reinterpret_cast<const float4*>(am + (size_t)k2 * NDIM + n + 4);
        v0 = make_float4(w0.x*m0.x, w0.y*m0.y, w0.z*m0.z, w0.w*m0.w);
        v1 = make_float4(w1.x*m1.x, w1.y*m1.y, w1.z*m1.z, w1.w*m1.w);
    } else {
        int k2 = kk - NPROW - NAROW;
        v0 = *reinterpret_cast<const float4*>(Wc + (size_t)k2 * NDIM + n);
        v1 = *reinterpret_cast<const float4*>(Wc + (size_t)k2 * NDIM + n + 4);
    }
    uint4 o;
    o.x = pack_h2(v0.x, v0.y); o.y = pack_h2(v0.z, v0.w);
    o.z = pack_h2(v1.x, v1.y); o.w = pack_h2(v1.z, v1.w);
    *reinterpret_cast<uint4*>(dst) = o;
}

// ---------------------------------------------------------------------------
// fp16 mma.sync GEMM: bulk-TMA, BK=64, 4-stage ring, distributed producers,
// register-direct epilogue (no smem staging, no epilogue barriers).
__global__ __launch_bounds__(NTHR, 1)
void gemm_exp_kernel(float* __restrict__ out) {
    extern __shared__ __align__(16) unsigned char smx[];
    const uint32_t sb0 = smem_u32(smx);          // [0..31] full, [32..63] free
    const int t   = threadIdx.x;
    const int wid = t >> 5;
    const int lid = t & 31;
    const int g   = lid >> 2;
    const int tig = lid & 3;

    const int per = GROUP * GRID_N;
    int bid = blockIdx.x;
    int grp = bid / per;
    int loc = bid - grp * per;
    int pm  = grp * GROUP + (loc & (GROUP - 1));
    int pn  = loc >> 4;
    const int m0 = pm * BM;
    const int n0 = pn * BN;

    const int wm = wid >> 3;
    const int wn = wid & 7;
    const int mbase = wm * 64;
    const int nbase = wn * 32;

    float acc[4][4][4];
#pragma unroll
    for (int i = 0; i < 4; i++)
#pragma unroll
        for (int j = 0; j < 4; j++)
#pragma unroll
            for (int q = 0; q < 4; q++) acc[i][j][q] = 0.f;

    if (t == 0) {
#pragma unroll
        for (int s = 0; s < STAGES; s++) {
            mbar_init(sb0 + s * 8, 1);           // full: tx-based
            mbar_init(sb0 + 32 + s * 8, 16);     // free: 16 warp arrivals
        }
    }
    __syncthreads();

    const unsigned char* srcA = g_Apack + (size_t)pm * NKT * A_TILE_B;
    const unsigned char* srcB = g_Wpack + (size_t)pn * NKT * B_TILE_B;

    auto issue_stage = [&](int slot, int ks) {
        const uint32_t mb  = sb0 + slot * 8;
        const uint32_t stg = sb0 + 64 + slot * STAGE_B;
        mbar_expect_tx(mb, STAGE_B);
        bulk_g2s(stg,            srcA + (size_t)ks * A_TILE_B, A_TILE_B, mb);
        bulk_g2s(stg + A_TILE_B, srcB + (size_t)ks * B_TILE_B, B_TILE_B, mb);
    };

    if (t == 0) {
#pragma unroll
        for (int s = 0; s < STAGES; s++) issue_stage(s, s);
    }

    const int laneRow = (lid & 7) + ((lid >> 3) & 1) * 8;   // 0..15
    const int laneHi  = (lid >> 4);                          // 0 or 1
    const uint32_t offA = (uint32_t)laneRow * APITCH + (uint32_t)(mbase + laneHi * 8) * 2;
    const uint32_t offB = (uint32_t)laneRow * BPITCH + (uint32_t)(nbase + laneHi * 8) * 2;

    int ph = 0;
    int fpown = 0;                       // producer-warp phase for its own slot
    const bool is_producer = (wid < STAGES) && (lid == 0);

    for (int kt = 0; kt < NKT; kt++) {
        const int slot = kt & (STAGES - 1);
        mbar_wait(sb0 + slot * 8, ph);

        const uint32_t stg = sb0 + 64 + slot * STAGE_B;
        const uint32_t pA = stg + offA;
        const uint32_t pB = stg + A_TILE_B + offB;

#pragma unroll
        for (int kk = 0; kk < BK; kk += 16) {
            uint32_t af[4][4], bf[4][2];
#pragma unroll
            for (int mf = 0; mf < 4; mf++) {
                uint32_t r[4];
                ldsm_x4_t(r, pA + kk * APITCH + mf * 32);
                af[mf][0] = r[0]; af[mf][1] = r[2]; af[mf][2] = r[1]; af[mf][3] = r[3];
            }
#pragma unroll
            for (int nf2 = 0; nf2 < 2; nf2++) {
                uint32_t r[4];
                ldsm_x4_t(r, pB + kk * BPITCH + nf2 * 32);
                bf[nf2 * 2][0]     = r[0]; bf[nf2 * 2][1]     = r[1];
                bf[nf2 * 2 + 1][0] = r[2]; bf[nf2 * 2 + 1][1] = r[3];
            }
#pragma unroll
            for (int mf = 0; mf < 4; mf++)
#pragma unroll
                for (int nf = 0; nf < 4; nf++)
                    mma_f16(acc[mf][nf], af[mf], bf[nf]);
        }

        if (lid == 0) mbar_arrive(sb0 + 32 + slot * 8);   // this warp done w/ stage
        // distributed producer: warp `slot` reissues its slot
        if (is_producer && wid == slot && kt + STAGES < NKT) {
            mbar_wait(sb0 + 32 + slot * 8, fpown);        // all 16 warps done
            issue_stage(slot, kt + STAGES);
            fpown ^= 1;
        }
        if (slot == STAGES - 1) ph ^= 1;
    }

    // ---- register-direct epilogue: exp -> gmem float2 + per-warp row partials ----
#pragma unroll
    for (int mf = 0; mf < 4; mf++) {
        const int r0 = mbase + mf * 16 + g;
        float* o0 = out + (size_t)(m0 + r0) * NDIM;
        float* o1 = o0 + (size_t)8 * NDIM;
        float s0 = 0.f, s1 = 0.f;
#pragma unroll
        for (int nf = 0; nf < 4; nf++) {
            const int n = n0 + nbase + nf * 8 + tig * 2;
            if (n < NDIM) {              // n even, NDIM even -> n+1 < NDIM too
                float e0 = __expf(acc[mf][nf][0]);
                float e1 = __expf(acc[mf][nf][1]);
                float e2 = __expf(acc[mf][nf][2]);
                float e3 = __expf(acc[mf][nf][3]);
                *reinterpret_cast<float2*>(o0 + n) = make_float2(e0, e1);
                *reinterpret_cast<float2*>(o1 + n) = make_float2(e2, e3);
                s0 += e0 + e1; s1 += e2 + e3;
            }
        }
        s0 += __shfl_xor_sync(0xffffffffu, s0, 1);
        s0 += __shfl_xor_sync(0xffffffffu, s0, 2);
        s1 += __shfl_xor_sync(0xffffffffu, s1, 1);
        s1 += __shfl_xor_sync(0xffffffffu, s1, 2);
        if (tig == 0) {
            g_part[(size_t)(m0 + r0)     * PW + pn * 8 + wn] = s0;
            g_part[(size_t)(m0 + r0 + 8) * PW + pn * 8 + wn] = s1;
        }
    }
}

// ---------------------------------------------------------------------------
__global__ void reduce_kernel(const float* __restrict__ loglib) {
    int row = blockIdx.x;
    float s = 0.f;
    for (int i = threadIdx.x; i < PW; i += 32) s += g_part[(size_t)row * PW + i];
#pragma unroll
    for (int o = 16; o > 0; o >>= 1) s += __shfl_down_sync(0xffffffffu, s, o);
    if (threadIdx.x == 0) g_scale[row] = expf(loglib[row]) / s;
}

__global__ void scale_kernel(float* __restrict__ out) {
    const int RF4 = NDIM / 4;
    long i = (long)blockIdx.x * blockDim.x + threadIdx.x;
    if (i >= (long)BDIM * RF4) return;
    int row = (int)(i / RF4);
    float s = g_scale[row];
    float4 v = reinterpret_cast<float4*>(out)[i];
    v.x *= s; v.y *= s; v.z *= s; v.w *= s;
    reinterpret_cast<float4*>(out)[i] = v;
}

// ---------------------------------------------------------------------------
extern "C" void kernel_launch(void* const* d_in, const int* in_sizes, int n_in,
                              void* d_out, int out_size) {
    const float* z      = (const float*)d_in[0];
    const float* loglib = (const float*)d_in[1];
    const float* cov    = (const float*)d_in[2];
    const float* mask   = (const float*)d_in[3];
    const float* amask  = (const float*)d_in[4];
    const float* Wm     = (const float*)d_in[5];
    const float* Wa     = (const float*)d_in[6];
    const float* Wc     = (const float*)d_in[7];
    float* out = (float*)d_out;

    cudaFuncSetAttribute(gemm_exp_kernel, cudaFuncAttributeMaxDynamicSharedMemorySize, SMEM_BYTES);

    build_Apack_kernel<<<GRID_M * NKT, 256>>>(z, cov);
    {
        size_t total = (size_t)GRID_N * NKT * BK * 33;
        build_Wpack_kernel<<<(unsigned)((total + 255) / 256), 256>>>(Wm, mask, Wa, amask, Wc);
    }
    gemm_exp_kernel<<<GRID_M * GRID_N, NTHR, SMEM_BYTES>>>(out);
    reduce_kernel<<<BDIM, 32>>>(loglib);
    {
        long total = (long)BDIM * (NDIM / 4);
        scale_kernel<<<(unsigned)((total + 255) / 256), 256>>>(out);
    }
}